// round 3
// baseline (speedup 1.0000x reference)
#include <cuda_runtime.h>
#include <math.h>

#define NN 20000
#define EE 320000
#define ISQ3 0.57735026918962576f
#define ISQ2 0.70710678118654752f

__device__ float g_Ssrc[NN*64];
__device__ float g_Sdst[NN*64];
__device__ float g_Vsrc[NN*96];   // [n][x*32+c]
__device__ float g_Vdst[NN*96];
__device__ float g_aex[EE*4];
__device__ unsigned int g_amax[NN*4];
__device__ float g_den[NN*4];
__device__ float g_agg[NN*160];   // per node: [h][16 hs + 24 hv]

__device__ __forceinline__ unsigned int fkey(float f) {
    unsigned int u = __float_as_uint(f);
    return (u & 0x80000000u) ? ~u : (u | 0x80000000u);
}
__device__ __forceinline__ float fdec(unsigned int k) {
    return __uint_as_float((k & 0x80000000u) ? (k ^ 0x80000000u) : ~k);
}
__device__ __forceinline__ float sigf(float x) { return 1.0f / (1.0f + expf(-x)); }

__global__ void k_init() {
    int st = gridDim.x * blockDim.x, t = blockIdx.x*blockDim.x + threadIdx.x;
    for (int i = t; i < NN*4; i += st) { g_amax[i] = 0u; g_den[i] = 0.f; }
    for (int i = t; i < NN*160; i += st) g_agg[i] = 0.f;
}

// ---- node norm + 4 linears: one warp per node ----
__global__ void __launch_bounds__(256) k_node(
    const float* __restrict__ node, const float* __restrict__ gs,
    const float* __restrict__ bs, const float* __restrict__ gv,
    const float* __restrict__ WsS, const float* __restrict__ WvS,
    const float* __restrict__ WsD, const float* __restrict__ WvD)
{
    int w = (blockIdx.x*blockDim.x + threadIdx.x) >> 5;
    int l = threadIdx.x & 31;
    if (w >= NN) return;
    const float* row = node + (size_t)w*160;
    float s0 = row[l], s1 = row[32+l];
    float sum = s0 + s1;
    #pragma unroll
    for (int o = 16; o >= 1; o >>= 1) sum += __shfl_xor_sync(~0u, sum, o);
    float mu = sum * (1.f/64.f);
    float d0 = s0-mu, d1 = s1-mu, vs = d0*d0 + d1*d1;
    #pragma unroll
    for (int o = 16; o >= 1; o >>= 1) vs += __shfl_xor_sync(~0u, vs, o);
    float inv = rsqrtf(vs*(1.f/64.f) + 1e-5f);
    float sn0 = d0*inv*gs[l] + bs[l];
    float sn1 = d1*inv*gs[32+l] + bs[32+l];
    float vx = row[64+3*l], vy = row[65+3*l], vz = row[66+3*l];
    float q = vx*vx + vy*vy + vz*vz;
    #pragma unroll
    for (int o = 16; o >= 1; o >>= 1) q += __shfl_xor_sync(~0u, q, o);
    float sc = gv[l] / sqrtf(q*(1.f/32.f) + 1e-5f);
    vx *= sc; vy *= sc; vz *= sc;
    // scalar linears: outputs at cols l, 32+l for src & dst
    float r0=0,r1=0,t0=0,t1=0;
    for (int c = 0; c < 32; c++) {
        float b = __shfl_sync(~0u, sn0, c);
        r0 += b*WsS[c*64+l]; r1 += b*WsS[c*64+32+l];
        t0 += b*WsD[c*64+l]; t1 += b*WsD[c*64+32+l];
    }
    for (int c = 0; c < 32; c++) {
        float b = __shfl_sync(~0u, sn1, c);
        r0 += b*WsS[(c+32)*64+l]; r1 += b*WsS[(c+32)*64+32+l];
        t0 += b*WsD[(c+32)*64+l]; t1 += b*WsD[(c+32)*64+32+l];
    }
    g_Ssrc[(size_t)w*64+l] = r0; g_Ssrc[(size_t)w*64+32+l] = r1;
    g_Sdst[(size_t)w*64+l] = t0; g_Sdst[(size_t)w*64+32+l] = t1;
    // vector linears: output channel l, 3 comps, src & dst
    float a0=0,a1=0,a2=0,b0=0,b1=0,b2=0;
    for (int c = 0; c < 32; c++) {
        float wx = __shfl_sync(~0u, vx, c), wy = __shfl_sync(~0u, vy, c), wz = __shfl_sync(~0u, vz, c);
        float ws = WvS[c*32+l], wd = WvD[c*32+l];
        a0 += wx*ws; a1 += wy*ws; a2 += wz*ws;
        b0 += wx*wd; b1 += wy*wd; b2 += wz*wd;
    }
    float* VS = g_Vsrc + (size_t)w*96; float* VD = g_Vdst + (size_t)w*96;
    VS[l] = a0; VS[32+l] = a1; VS[64+l] = a2;
    VD[l] = b0; VD[32+l] = b1; VD[64+l] = b2;
}

// ---- edge pass 1: attention logits + segment max; warp per edge ----
__global__ void __launch_bounds__(512) k_edge1(
    const int* __restrict__ ei, const float* __restrict__ rbf,
    const float* __restrict__ rsh, const float* __restrict__ Wr,
    const float* __restrict__ Wa, const float* __restrict__ ad)
{
    __shared__ float sm[11328];
    float* sWr = sm; float* sWa = sm+3584; float* sAd = sm+9728; float* sM1 = sm+9792;
    int tid = threadIdx.x;
    for (int i = tid; i < 3584; i += 512) sWr[i] = Wr[i];
    for (int i = tid; i < 6144; i += 512) sWa[i] = Wa[i];
    if (tid < 64) sAd[tid] = ad[tid];
    __syncthreads();
    int l = tid & 31, wid = tid >> 5;
    float* m1 = sM1 + wid*96;
    int gw = blockIdx.x*16 + wid, tw = gridDim.x*16;
    for (int e = gw; e < EE; e += tw) {
        int src = ei[e], dst = ei[EE+e];
        float y0 = rsh[4*e], y1x = rsh[4*e+1], y1y = rsh[4*e+2], y1z = rsh[4*e+3];
        float rv = (l < 16) ? rbf[16*e+l] : 0.f;
        float w1[7] = {0,0,0,0,0,0,0};
        #pragma unroll
        for (int b = 0; b < 16; b++) {
            float rb = __shfl_sync(~0u, rv, b);
            #pragma unroll
            for (int j = 0; j < 7; j++) w1[j] += rb * sWr[b*224 + l + 32*j];
        }
        float sc0 = g_Ssrc[src*64+l]    + g_Sdst[dst*64+l];
        float sc1 = g_Ssrc[src*64+32+l] + g_Sdst[dst*64+32+l];
        float vx = g_Vsrc[src*96+l]    + g_Vdst[dst*96+l];
        float vy = g_Vsrc[src*96+32+l] + g_Vdst[dst*96+32+l];
        float vz = g_Vsrc[src*96+64+l] + g_Vdst[dst*96+64+l];
        float ms0 = w1[0]*sc0*y0, ms1 = w1[1]*sc1*y0;
        float ms2 = w1[5]*(vx*y1x + vy*y1y + vz*y1z)*ISQ3;
        __syncwarp();
        m1[l] = ms0; m1[32+l] = ms1; m1[64+l] = ms2;
        __syncwarp();
        float aA = 0.f, aB = 0.f;
        #pragma unroll 8
        for (int k = 0; k < 96; k++) {
            float m = m1[k];
            aA += m*sWa[k*64+l]; aB += m*sWa[k*64+32+l];
        }
        aA = aA > 0.f ? aA : 0.2f*aA;  aB = aB > 0.f ? aB : 0.2f*aB;
        aA *= sAd[l]; aB *= sAd[32+l];
        #pragma unroll
        for (int o = 8; o >= 1; o >>= 1) {
            aA += __shfl_xor_sync(~0u, aA, o, 16);
            aB += __shfl_xor_sync(~0u, aB, o, 16);
        }
        if (l == 0) {
            g_aex[4*e] = aA; g_aex[4*e+2] = aB;
            atomicMax(&g_amax[4*dst],   fkey(aA));
            atomicMax(&g_amax[4*dst+2], fkey(aB));
        } else if (l == 16) {
            g_aex[4*e+1] = aA; g_aex[4*e+3] = aB;
            atomicMax(&g_amax[4*dst+1], fkey(aA));
            atomicMax(&g_amax[4*dst+3], fkey(aB));
        }
        __syncwarp();
    }
}

__global__ void k_soft(const int* __restrict__ ei) {
    int i = blockIdx.x*blockDim.x + threadIdx.x;
    if (i >= EE*4) return;
    int e = i >> 2, h = i & 3;
    int dst = ei[EE+e];
    float am = fdec(g_amax[4*dst+h]);
    if (!isfinite(am)) am = 0.f;
    float ex = expf(g_aex[i] - am);
    g_aex[i] = ex;
    atomicAdd(&g_den[4*dst+h], ex);
}

// ---- edge pass 2: value path + scatter; warp per edge, 136KB smem ----
__global__ void __launch_bounds__(512) k_edge2(
    const int* __restrict__ ei, const float* __restrict__ rbf,
    const float* __restrict__ rsh, const float* __restrict__ Wr,
    const float* __restrict__ Wval, const float* __restrict__ Wvv,
    const float* __restrict__ Wg,
    const float* __restrict__ w2ss, const float* __restrict__ w2sv,
    const float* __restrict__ w2vs, const float* __restrict__ w2v0,
    const float* __restrict__ w2v1,
    const float* __restrict__ Wvl, const float* __restrict__ Wvv2)
{
    extern __shared__ float sm[];
    float* sWr = sm;            // 3584
    float* sWval = sm+3584;     // 6144
    float* sWvv = sm+9728;      // 4096
    float* sWg = sm+13824;      // 2048
    float* sWvl = sm+15872;     // 6144
    float* sWvv2 = sm+22016;    // 4096
    float* sw2 = sm+26112;      // 224
    float* sB = sm+26336;       // 16 * 480
    int tid = threadIdx.x;
    for (int i = tid; i < 3584; i += 512) sWr[i] = Wr[i];
    for (int i = tid; i < 6144; i += 512) { sWval[i] = Wval[i]; sWvl[i] = Wvl[i]; }
    for (int i = tid; i < 4096; i += 512) { sWvv[i] = Wvv[i]; sWvv2[i] = Wvv2[i]; }
    for (int i = tid; i < 2048; i += 512) sWg[i] = Wg[i];
    if (tid < 64) { sw2[tid] = w2ss[tid]; sw2[64+tid] = w2sv[tid]; }
    if (tid < 32) { sw2[128+tid] = w2vs[tid]; sw2[160+tid] = w2v0[tid]; sw2[192+tid] = w2v1[tid]; }
    __syncthreads();
    int l = tid & 31, wid = tid >> 5;
    float* b96 = sB + wid*480;
    float* b384 = b96 + 96;
    int gw = blockIdx.x*16 + wid, tw = gridDim.x*16;
    for (int e = gw; e < EE; e += tw) {
        int src = ei[e], dst = ei[EE+e];
        float y0 = rsh[4*e], y1x = rsh[4*e+1], y1y = rsh[4*e+2], y1z = rsh[4*e+3];
        float rv = (l < 16) ? rbf[16*e+l] : 0.f;
        float w1[7] = {0,0,0,0,0,0,0};
        #pragma unroll
        for (int b = 0; b < 16; b++) {
            float rb = __shfl_sync(~0u, rv, b);
            #pragma unroll
            for (int j = 0; j < 7; j++) w1[j] += rb * sWr[b*224 + l + 32*j];
        }
        float sc0 = g_Ssrc[src*64+l]    + g_Sdst[dst*64+l];
        float sc1 = g_Ssrc[src*64+32+l] + g_Sdst[dst*64+32+l];
        float vx = g_Vsrc[src*96+l]    + g_Vdst[dst*96+l];
        float vy = g_Vsrc[src*96+32+l] + g_Vdst[dst*96+32+l];
        float vz = g_Vsrc[src*96+64+l] + g_Vdst[dst*96+64+l];
        float ms0 = w1[0]*sc0*y0, ms1 = w1[1]*sc1*y0;
        float ms2 = w1[5]*(vx*y1x + vy*y1y + vz*y1z)*ISQ3;
        float cx = vy*y1z - vz*y1y, cy = vz*y1x - vx*y1z, cz = vx*y1y - vy*y1x;
        __syncwarp();
        b96[l] = ms0; b96[32+l] = ms1; b96[64+l] = ms2;
        b384[l]    = w1[2]*sc0*y1x; b384[128+l]    = w1[2]*sc0*y1y; b384[256+l]    = w1[2]*sc0*y1z;
        b384[32+l] = w1[3]*sc1*y1x; b384[160+l]    = w1[3]*sc1*y1y; b384[288+l]    = w1[3]*sc1*y1z;
        b384[64+l] = w1[4]*vx*y0;   b384[192+l]    = w1[4]*vy*y0;   b384[320+l]    = w1[4]*vz*y0;
        b384[96+l] = w1[6]*cx*ISQ2; b384[224+l]    = w1[6]*cy*ISQ2; b384[352+l]    = w1[6]*cz*ISQ2;
        __syncwarp();
        float vs0 = 0.f, vs1 = 0.f;
        #pragma unroll 8
        for (int k = 0; k < 96; k++) {
            float m = b96[k];
            vs0 += m*sWval[k*64+l]; vs1 += m*sWval[k*64+32+l];
        }
        __syncwarp();
        b96[l] = vs0; b96[32+l] = vs1;
        __syncwarp();
        float ga = 0.f;
        #pragma unroll 8
        for (int k = 0; k < 64; k++) ga += b96[k]*sWg[k*32+l];
        float gate = sigf(ga);
        float v0 = 0.f, v1 = 0.f, v2 = 0.f;
        #pragma unroll 8
        for (int c = 0; c < 128; c++) {
            float w = sWvv[c*32+l];
            v0 += b384[c]*w; v1 += b384[128+c]*w; v2 += b384[256+c]*w;
        }
        v0 *= gate; v1 *= gate; v2 *= gate;
        float ss0 = sigf(vs0), ss1 = sigf(vs1);
        float n0 = sw2[l]*ss0*y0, n1 = sw2[32+l]*ss1*y0;
        float n2 = sw2[160+l]*(v0*y1x + v1*y1y + v2*y1z)*ISQ3;
        float c2x = v1*y1z - v2*y1y, c2y = v2*y1x - v0*y1z, c2z = v0*y1y - v1*y1x;
        __syncwarp();
        b96[l] = n0; b96[32+l] = n1; b96[64+l] = n2;
        b384[l]    = sw2[64+l]*ss0*y1x; b384[128+l] = sw2[64+l]*ss0*y1y; b384[256+l] = sw2[64+l]*ss0*y1z;
        b384[32+l] = sw2[96+l]*ss1*y1x; b384[160+l] = sw2[96+l]*ss1*y1y; b384[288+l] = sw2[96+l]*ss1*y1z;
        b384[64+l] = sw2[128+l]*v0*y0;  b384[192+l] = sw2[128+l]*v1*y0;  b384[320+l] = sw2[128+l]*v2*y0;
        b384[96+l] = sw2[192+l]*c2x*ISQ2; b384[224+l] = sw2[192+l]*c2y*ISQ2; b384[352+l] = sw2[192+l]*c2z*ISQ2;
        __syncwarp();
        float hs0 = 0.f, hs1 = 0.f;
        #pragma unroll 8
        for (int k = 0; k < 96; k++) {
            float m = b96[k];
            hs0 += m*sWvl[k*64+l]; hs1 += m*sWvl[k*64+32+l];
        }
        float h0 = 0.f, h1 = 0.f, h2 = 0.f;
        #pragma unroll 8
        for (int c = 0; c < 128; c++) {
            float w = sWvv2[c*32+l];
            h0 += b384[c]*w; h1 += b384[128+c]*w; h2 += b384[256+c]*w;
        }
        // attention weights & scatter
        int hA = l >> 4, hV = l >> 3;
        float al0 = g_aex[4*e+hA]   / (g_den[4*dst+hA]   + 1e-16f);
        float al1 = g_aex[4*e+2+hA] / (g_den[4*dst+2+hA] + 1e-16f);
        float alv = g_aex[4*e+hV]   / (g_den[4*dst+hV]   + 1e-16f);
        float* ag = g_agg + (size_t)dst*160;
        atomicAdd(ag + hA*40 + (l&15), al0*hs0);
        atomicAdd(ag + (2+hA)*40 + (l&15), al1*hs1);
        int vb = hV*40 + 16 + (l&7)*3;
        atomicAdd(ag+vb,   alv*h0);
        atomicAdd(ag+vb+1, alv*h1);
        atomicAdd(ag+vb+2, alv*h2);
        __syncwarp();
    }
}

// ---- output projection + residual: warp per node ----
__global__ void __launch_bounds__(256) k_out(
    const float* __restrict__ node, const float* __restrict__ Wps,
    const float* __restrict__ Wpv, float* __restrict__ out)
{
    int w = (blockIdx.x*blockDim.x + threadIdx.x) >> 5;
    int l = threadIdx.x & 31;
    if (w >= NN) return;
    const float* ag = g_agg + (size_t)w*160;
    float a0 = ag[(l>>4)*40 + (l&15)];
    float a1 = ag[(2+(l>>4))*40 + (l&15)];
    int vb = (l>>3)*40 + 16 + (l&7)*3;
    float vx = ag[vb], vy = ag[vb+1], vz = ag[vb+2];
    float s0 = 0.f, s1 = 0.f;
    for (int c = 0; c < 32; c++) {
        float b = __shfl_sync(~0u, a0, c);
        s0 += b*Wps[c*64+l]; s1 += b*Wps[c*64+32+l];
    }
    for (int c = 0; c < 32; c++) {
        float b = __shfl_sync(~0u, a1, c);
        s0 += b*Wps[(c+32)*64+l]; s1 += b*Wps[(c+32)*64+32+l];
    }
    float o0 = 0.f, o1 = 0.f, o2 = 0.f;
    for (int c = 0; c < 32; c++) {
        float ww = Wpv[c*32+l];
        o0 += __shfl_sync(~0u, vx, c)*ww;
        o1 += __shfl_sync(~0u, vy, c)*ww;
        o2 += __shfl_sync(~0u, vz, c)*ww;
    }
    const float* nr = node + (size_t)w*160;
    float* orow = out + (size_t)w*160;
    orow[l] = nr[l] + s0;
    orow[32+l] = nr[32+l] + s1;
    orow[64+3*l] = nr[64+3*l] + o0;
    orow[65+3*l] = nr[65+3*l] + o1;
    orow[66+3*l] = nr[66+3*l] + o2;
}

extern "C" void kernel_launch(void* const* d_in, const int* in_sizes, int n_in,
                              void* d_out, int out_size) {
    // locate edge_index by its unique element count (2*E)
    int ei_pos = -1;
    for (int i = 0; i < n_in; i++) if (in_sizes[i] == 2*EE) { ei_pos = i; break; }
    const float* p[25]; int j = 0;
    for (int i = 0; i < n_in; i++) { if (i == ei_pos) continue; p[j++] = (const float*)d_in[i]; }
    const float *node = p[0], *rbf = p[1], *rsh = p[2], *gs = p[3], *bs = p[4], *gv = p[5],
                *WsS = p[6], *WvS = p[7], *WsD = p[8], *WvD = p[9], *Wr = p[10],
                *Wa = p[11], *ad = p[12], *Wval = p[13], *Wvv = p[14], *Wg = p[15],
                *w2ss = p[16], *w2sv = p[17], *w2vs = p[18], *w2v0 = p[19], *w2v1 = p[20],
                *Wvl = p[21], *Wvv2 = p[22], *Wps = p[23], *Wpv = p[24];
    const int* ei = (const int*)d_in[ei_pos];
    float* out = (float*)d_out;

    cudaFuncSetAttribute(k_edge2, cudaFuncAttributeMaxDynamicSharedMemorySize, 34016*4);

    k_init<<<256, 256>>>();
    k_node<<<(NN*32 + 255)/256, 256>>>(node, gs, bs, gv, WsS, WvS, WsD, WvD);
    k_edge1<<<296, 512>>>(ei, rbf, rsh, Wr, Wa, ad);
    k_soft<<<(EE*4 + 255)/256, 256>>>(ei);
    k_edge2<<<148, 512, 34016*4>>>(ei, rbf, rsh, Wr, Wval, Wvv, Wg,
                                   w2ss, w2sv, w2vs, w2v0, w2v1, Wvl, Wvv2);
    k_out<<<(NN*32 + 255)/256, 256>>>(node, Wps, Wpv, out);
}

// round 4
// speedup vs baseline: 1.0372x; 1.0372x over previous
#include <cuda_runtime.h>
#include <math.h>

#define NN 20000
#define EE 320000
#define ISQ3 0.57735026918962576f
#define ISQ2 0.70710678118654752f

__device__ float g_Ssrc[NN*64];
__device__ float g_Sdst[NN*64];
__device__ float g_Vsrc[NN*96];   // [n][x*32+c]
__device__ float g_Vdst[NN*96];
__device__ float g_aex[EE*4];
__device__ unsigned int g_amax[NN*4];
__device__ float g_den[NN*4];
__device__ float g_agg[NN*160];   // per node: [h][16 hs + 24 hv]

__device__ __forceinline__ unsigned int fkey(float f) {
    unsigned int u = __float_as_uint(f);
    return (u & 0x80000000u) ? ~u : (u | 0x80000000u);
}
__device__ __forceinline__ float fdec(unsigned int k) {
    return __uint_as_float((k & 0x80000000u) ? (k ^ 0x80000000u) : ~k);
}
__device__ __forceinline__ float sigf(float x) { return 1.0f / (1.0f + expf(-x)); }

__global__ void k_init() {
    int st = gridDim.x * blockDim.x, t = blockIdx.x*blockDim.x + threadIdx.x;
    for (int i = t; i < NN*4; i += st) { g_amax[i] = 0u; g_den[i] = 0.f; }
    for (int i = t; i < NN*160; i += st) g_agg[i] = 0.f;
}

// ---- node norm + 4 linears: one warp per node ----
__global__ void __launch_bounds__(256) k_node(
    const float* __restrict__ node, const float* __restrict__ gs,
    const float* __restrict__ bs, const float* __restrict__ gv,
    const float* __restrict__ WsS, const float* __restrict__ WvS,
    const float* __restrict__ WsD, const float* __restrict__ WvD)
{
    int w = (blockIdx.x*blockDim.x + threadIdx.x) >> 5;
    int l = threadIdx.x & 31;
    if (w >= NN) return;
    const float* row = node + (size_t)w*160;
    float s0 = row[l], s1 = row[32+l];
    float sum = s0 + s1;
    #pragma unroll
    for (int o = 16; o >= 1; o >>= 1) sum += __shfl_xor_sync(~0u, sum, o);
    float mu = sum * (1.f/64.f);
    float d0 = s0-mu, d1 = s1-mu, vs = d0*d0 + d1*d1;
    #pragma unroll
    for (int o = 16; o >= 1; o >>= 1) vs += __shfl_xor_sync(~0u, vs, o);
    float inv = rsqrtf(vs*(1.f/64.f) + 1e-5f);
    float sn0 = d0*inv*gs[l] + bs[l];
    float sn1 = d1*inv*gs[32+l] + bs[32+l];
    float vx = row[64+3*l], vy = row[65+3*l], vz = row[66+3*l];
    float q = vx*vx + vy*vy + vz*vz;
    #pragma unroll
    for (int o = 16; o >= 1; o >>= 1) q += __shfl_xor_sync(~0u, q, o);
    float sc = gv[l] / sqrtf(q*(1.f/32.f) + 1e-5f);
    vx *= sc; vy *= sc; vz *= sc;
    float r0=0,r1=0,t0=0,t1=0;
    for (int c = 0; c < 32; c++) {
        float b = __shfl_sync(~0u, sn0, c);
        r0 += b*WsS[c*64+l]; r1 += b*WsS[c*64+32+l];
        t0 += b*WsD[c*64+l]; t1 += b*WsD[c*64+32+l];
    }
    for (int c = 0; c < 32; c++) {
        float b = __shfl_sync(~0u, sn1, c);
        r0 += b*WsS[(c+32)*64+l]; r1 += b*WsS[(c+32)*64+32+l];
        t0 += b*WsD[(c+32)*64+l]; t1 += b*WsD[(c+32)*64+32+l];
    }
    g_Ssrc[(size_t)w*64+l] = r0; g_Ssrc[(size_t)w*64+32+l] = r1;
    g_Sdst[(size_t)w*64+l] = t0; g_Sdst[(size_t)w*64+32+l] = t1;
    float a0=0,a1=0,a2=0,b0=0,b1=0,b2=0;
    for (int c = 0; c < 32; c++) {
        float wx = __shfl_sync(~0u, vx, c), wy = __shfl_sync(~0u, vy, c), wz = __shfl_sync(~0u, vz, c);
        float ws = WvS[c*32+l], wd = WvD[c*32+l];
        a0 += wx*ws; a1 += wy*ws; a2 += wz*ws;
        b0 += wx*wd; b1 += wy*wd; b2 += wz*wd;
    }
    float* VS = g_Vsrc + (size_t)w*96; float* VD = g_Vdst + (size_t)w*96;
    VS[l] = a0; VS[32+l] = a1; VS[64+l] = a2;
    VD[l] = b0; VD[32+l] = b1; VD[64+l] = b2;
}

// ---- edge pass 1: attention logits + segment max; warp per edge ----
// smem (floats): WrT 224x20 @0 | WaT 64x100 @4480 | Ad 64 @10880 | M1 16x96 @10944
__global__ void __launch_bounds__(512) k_edge1(
    const int* __restrict__ ei, const float* __restrict__ rbf,
    const float* __restrict__ rsh, const float* __restrict__ Wr,
    const float* __restrict__ Wa, const float* __restrict__ ad)
{
    extern __shared__ float sm[];
    float* sWrT = sm; float* sWaT = sm+4480; float* sAd = sm+10880; float* sM1 = sm+10944;
    int tid = threadIdx.x;
    for (int i = tid; i < 3584; i += 512) { int b = i/224, c = i%224; sWrT[c*20+b] = Wr[i]; }
    for (int i = tid; i < 6144; i += 512) { int k = i/64, o = i%64; sWaT[o*100+k] = Wa[i]; }
    if (tid < 64) sAd[tid] = ad[tid];
    __syncthreads();
    int l = tid & 31, wid = tid >> 5;
    float* m1 = sM1 + wid*96;
    int gw = blockIdx.x*16 + wid, tw = gridDim.x*16;
    for (int e = gw; e < EE; e += tw) {
        int src = ei[e], dst = ei[EE+e];
        float4 ys = *(const float4*)&rsh[4*e];
        float y0 = ys.x, y1x = ys.y, y1y = ys.z, y1z = ys.w;
        float rv = (l < 16) ? rbf[16*e+l] : 0.f;
        float rb[16];
        #pragma unroll
        for (int b = 0; b < 16; b++) rb[b] = __shfl_sync(~0u, rv, b);
        float w10 = 0.f, w11 = 0.f, w15 = 0.f;
        {
            const float4* r0 = (const float4*)&sWrT[l*20];
            const float4* r1 = (const float4*)&sWrT[(l+32)*20];
            const float4* r5 = (const float4*)&sWrT[(l+160)*20];
            #pragma unroll
            for (int q = 0; q < 4; q++) {
                float4 a = r0[q], b = r1[q], c = r5[q];
                w10 += rb[4*q]*a.x; w10 += rb[4*q+1]*a.y; w10 += rb[4*q+2]*a.z; w10 += rb[4*q+3]*a.w;
                w11 += rb[4*q]*b.x; w11 += rb[4*q+1]*b.y; w11 += rb[4*q+2]*b.z; w11 += rb[4*q+3]*b.w;
                w15 += rb[4*q]*c.x; w15 += rb[4*q+1]*c.y; w15 += rb[4*q+2]*c.z; w15 += rb[4*q+3]*c.w;
            }
        }
        float sc0 = g_Ssrc[src*64+l]    + g_Sdst[dst*64+l];
        float sc1 = g_Ssrc[src*64+32+l] + g_Sdst[dst*64+32+l];
        float vx = g_Vsrc[src*96+l]    + g_Vdst[dst*96+l];
        float vy = g_Vsrc[src*96+32+l] + g_Vdst[dst*96+32+l];
        float vz = g_Vsrc[src*96+64+l] + g_Vdst[dst*96+64+l];
        float ms0 = w10*sc0*y0, ms1 = w11*sc1*y0;
        float ms2 = w15*(vx*y1x + vy*y1y + vz*y1z)*ISQ3;
        __syncwarp();
        m1[l] = ms0; m1[32+l] = ms1; m1[64+l] = ms2;
        __syncwarp();
        float aA = 0.f, aB = 0.f;
        {
            const float4* m4 = (const float4*)m1;
            const float4* wa = (const float4*)&sWaT[l*100];
            const float4* wb = (const float4*)&sWaT[(32+l)*100];
            #pragma unroll 8
            for (int q = 0; q < 24; q++) {
                float4 m = m4[q], a = wa[q], b = wb[q];
                aA += m.x*a.x; aA += m.y*a.y; aA += m.z*a.z; aA += m.w*a.w;
                aB += m.x*b.x; aB += m.y*b.y; aB += m.z*b.z; aB += m.w*b.w;
            }
        }
        aA = aA > 0.f ? aA : 0.2f*aA;  aB = aB > 0.f ? aB : 0.2f*aB;
        aA *= sAd[l]; aB *= sAd[32+l];
        #pragma unroll
        for (int o = 8; o >= 1; o >>= 1) {
            aA += __shfl_xor_sync(~0u, aA, o, 16);
            aB += __shfl_xor_sync(~0u, aB, o, 16);
        }
        if (l == 0) {
            g_aex[4*e] = aA; g_aex[4*e+2] = aB;
            atomicMax(&g_amax[4*dst],   fkey(aA));
            atomicMax(&g_amax[4*dst+2], fkey(aB));
        } else if (l == 16) {
            g_aex[4*e+1] = aA; g_aex[4*e+3] = aB;
            atomicMax(&g_amax[4*dst+1], fkey(aA));
            atomicMax(&g_amax[4*dst+3], fkey(aB));
        }
        __syncwarp();
    }
}

__global__ void k_soft(const int* __restrict__ ei) {
    int i = blockIdx.x*blockDim.x + threadIdx.x;
    if (i >= EE*4) return;
    int e = i >> 2, h = i & 3;
    int dst = ei[EE+e];
    float am = fdec(g_amax[4*dst+h]);
    if (!isfinite(am)) am = 0.f;
    float ex = expf(g_aex[i] - am);
    g_aex[i] = ex;
    atomicAdd(&g_den[4*dst+h], ex);
}

// ---- edge pass 2: value path + scatter; warp per edge ----
// smem (floats): WrT 224x20 @0 | WvalT 64x100 @4480 | WgT 32x68 @10880 |
//                WvvT 32x132 @13056 | WvlT 64x100 @17280 | Wvv2T 32x132 @23680 |
//                w2 224 @27904 | staging 16x480 @28128   (total 35808 fl = 143232 B)
__global__ void __launch_bounds__(512) k_edge2(
    const int* __restrict__ ei, const float* __restrict__ rbf,
    const float* __restrict__ rsh, const float* __restrict__ Wr,
    const float* __restrict__ Wval, const float* __restrict__ Wvv,
    const float* __restrict__ Wg,
    const float* __restrict__ w2ss, const float* __restrict__ w2sv,
    const float* __restrict__ w2vs, const float* __restrict__ w2v0,
    const float* __restrict__ w2v1,
    const float* __restrict__ Wvl, const float* __restrict__ Wvv2)
{
    extern __shared__ float sm[];
    float* sWrT   = sm;
    float* sWvalT = sm+4480;
    float* sWgT   = sm+10880;
    float* sWvvT  = sm+13056;
    float* sWvlT  = sm+17280;
    float* sWvv2T = sm+23680;
    float* sw2    = sm+27904;
    float* sB     = sm+28128;
    int tid = threadIdx.x;
    for (int i = tid; i < 3584; i += 512) { int b = i/224, c = i%224; sWrT[c*20+b] = Wr[i]; }
    for (int i = tid; i < 6144; i += 512) { int k = i/64, o = i%64; sWvalT[o*100+k] = Wval[i]; sWvlT[o*100+k] = Wvl[i]; }
    for (int i = tid; i < 2048; i += 512) { int k = i/32, o = i%32; sWgT[o*68+k] = Wg[i]; }
    for (int i = tid; i < 4096; i += 512) { int k = i/32, o = i%32; sWvvT[o*132+k] = Wvv[i]; sWvv2T[o*132+k] = Wvv2[i]; }
    if (tid < 64) { sw2[tid] = w2ss[tid]; sw2[64+tid] = w2sv[tid]; }
    if (tid < 32) { sw2[128+tid] = w2vs[tid]; sw2[160+tid] = w2v0[tid]; sw2[192+tid] = w2v1[tid]; }
    __syncthreads();
    int l = tid & 31, wid = tid >> 5;
    float* b96 = sB + wid*480;
    float* b384 = b96 + 96;
    int gw = blockIdx.x*16 + wid, tw = gridDim.x*16;
    for (int e = gw; e < EE; e += tw) {
        int src = ei[e], dst = ei[EE+e];
        float4 ys = *(const float4*)&rsh[4*e];
        float y0 = ys.x, y1x = ys.y, y1y = ys.z, y1z = ys.w;
        float rv = (l < 16) ? rbf[16*e+l] : 0.f;
        float rb[16];
        #pragma unroll
        for (int b = 0; b < 16; b++) rb[b] = __shfl_sync(~0u, rv, b);
        float w1[7] = {0,0,0,0,0,0,0};
        #pragma unroll
        for (int j = 0; j < 7; j++) {
            const float4* wr = (const float4*)&sWrT[(l+32*j)*20];
            #pragma unroll
            for (int q = 0; q < 4; q++) {
                float4 w = wr[q];
                w1[j] += rb[4*q]*w.x; w1[j] += rb[4*q+1]*w.y;
                w1[j] += rb[4*q+2]*w.z; w1[j] += rb[4*q+3]*w.w;
            }
        }
        float sc0 = g_Ssrc[src*64+l]    + g_Sdst[dst*64+l];
        float sc1 = g_Ssrc[src*64+32+l] + g_Sdst[dst*64+32+l];
        float vx = g_Vsrc[src*96+l]    + g_Vdst[dst*96+l];
        float vy = g_Vsrc[src*96+32+l] + g_Vdst[dst*96+32+l];
        float vz = g_Vsrc[src*96+64+l] + g_Vdst[dst*96+64+l];
        float ms0 = w1[0]*sc0*y0, ms1 = w1[1]*sc1*y0;
        float ms2 = w1[5]*(vx*y1x + vy*y1y + vz*y1z)*ISQ3;
        float cx = vy*y1z - vz*y1y, cy = vz*y1x - vx*y1z, cz = vx*y1y - vy*y1x;
        __syncwarp();
        b96[l] = ms0; b96[32+l] = ms1; b96[64+l] = ms2;
        b384[l]    = w1[2]*sc0*y1x; b384[128+l] = w1[2]*sc0*y1y; b384[256+l] = w1[2]*sc0*y1z;
        b384[32+l] = w1[3]*sc1*y1x; b384[160+l] = w1[3]*sc1*y1y; b384[288+l] = w1[3]*sc1*y1z;
        b384[64+l] = w1[4]*vx*y0;   b384[192+l] = w1[4]*vy*y0;   b384[320+l] = w1[4]*vz*y0;
        b384[96+l] = w1[6]*cx*ISQ2; b384[224+l] = w1[6]*cy*ISQ2; b384[352+l] = w1[6]*cz*ISQ2;
        __syncwarp();
        float vs0 = 0.f, vs1 = 0.f;
        {
            const float4* m4 = (const float4*)b96;
            const float4* wa = (const float4*)&sWvalT[l*100];
            const float4* wb = (const float4*)&sWvalT[(32+l)*100];
            #pragma unroll 8
            for (int q = 0; q < 24; q++) {
                float4 m = m4[q], a = wa[q], b = wb[q];
                vs0 += m.x*a.x; vs0 += m.y*a.y; vs0 += m.z*a.z; vs0 += m.w*a.w;
                vs1 += m.x*b.x; vs1 += m.y*b.y; vs1 += m.z*b.z; vs1 += m.w*b.w;
            }
        }
        __syncwarp();
        b96[l] = vs0; b96[32+l] = vs1;
        __syncwarp();
        float ga = 0.f;
        {
            const float4* m4 = (const float4*)b96;
            const float4* wg = (const float4*)&sWgT[l*68];
            #pragma unroll
            for (int q = 0; q < 16; q++) {
                float4 m = m4[q], w = wg[q];
                ga += m.x*w.x; ga += m.y*w.y; ga += m.z*w.z; ga += m.w*w.w;
            }
        }
        float gate = sigf(ga);
        float v0 = 0.f, v1 = 0.f, v2 = 0.f;
        {
            const float4* wp = (const float4*)&sWvvT[l*132];
            const float4* mx = (const float4*)b384;
            const float4* my = mx + 32;
            const float4* mz = mx + 64;
            #pragma unroll 8
            for (int q = 0; q < 32; q++) {
                float4 w = wp[q], a = mx[q], b = my[q], c = mz[q];
                v0 += a.x*w.x; v0 += a.y*w.y; v0 += a.z*w.z; v0 += a.w*w.w;
                v1 += b.x*w.x; v1 += b.y*w.y; v1 += b.z*w.z; v1 += b.w*w.w;
                v2 += c.x*w.x; v2 += c.y*w.y; v2 += c.z*w.z; v2 += c.w*w.w;
            }
        }
        v0 *= gate; v1 *= gate; v2 *= gate;
        float ss0 = sigf(vs0), ss1 = sigf(vs1);
        float n0 = sw2[l]*ss0*y0, n1 = sw2[32+l]*ss1*y0;
        float n2 = sw2[160+l]*(v0*y1x + v1*y1y + v2*y1z)*ISQ3;
        float c2x = v1*y1z - v2*y1y, c2y = v2*y1x - v0*y1z, c2z = v0*y1y - v1*y1x;
        __syncwarp();
        b96[l] = n0; b96[32+l] = n1; b96[64+l] = n2;
        b384[l]    = sw2[64+l]*ss0*y1x; b384[128+l] = sw2[64+l]*ss0*y1y; b384[256+l] = sw2[64+l]*ss0*y1z;
        b384[32+l] = sw2[96+l]*ss1*y1x; b384[160+l] = sw2[96+l]*ss1*y1y; b384[288+l] = sw2[96+l]*ss1*y1z;
        b384[64+l] = sw2[128+l]*v0*y0;  b384[192+l] = sw2[128+l]*v1*y0;  b384[320+l] = sw2[128+l]*v2*y0;
        b384[96+l] = sw2[192+l]*c2x*ISQ2; b384[224+l] = sw2[192+l]*c2y*ISQ2; b384[352+l] = sw2[192+l]*c2z*ISQ2;
        __syncwarp();
        float hs0 = 0.f, hs1 = 0.f;
        {
            const float4* m4 = (const float4*)b96;
            const float4* wa = (const float4*)&sWvlT[l*100];
            const float4* wb = (const float4*)&sWvlT[(32+l)*100];
            #pragma unroll 8
            for (int q = 0; q < 24; q++) {
                float4 m = m4[q], a = wa[q], b = wb[q];
                hs0 += m.x*a.x; hs0 += m.y*a.y; hs0 += m.z*a.z; hs0 += m.w*a.w;
                hs1 += m.x*b.x; hs1 += m.y*b.y; hs1 += m.z*b.z; hs1 += m.w*b.w;
            }
        }
        float h0 = 0.f, h1 = 0.f, h2 = 0.f;
        {
            const float4* wp = (const float4*)&sWvv2T[l*132];
            const float4* mx = (const float4*)b384;
            const float4* my = mx + 32;
            const float4* mz = mx + 64;
            #pragma unroll 8
            for (int q = 0; q < 32; q++) {
                float4 w = wp[q], a = mx[q], b = my[q], c = mz[q];
                h0 += a.x*w.x; h0 += a.y*w.y; h0 += a.z*w.z; h0 += a.w*w.w;
                h1 += b.x*w.x; h1 += b.y*w.y; h1 += b.z*w.z; h1 += b.w*w.w;
                h2 += c.x*w.x; h2 += c.y*w.y; h2 += c.z*w.z; h2 += c.w*w.w;
            }
        }
        int hA = l >> 4, hV = l >> 3;
        float al0 = g_aex[4*e+hA]   / (g_den[4*dst+hA]   + 1e-16f);
        float al1 = g_aex[4*e+2+hA] / (g_den[4*dst+2+hA] + 1e-16f);
        float alv = g_aex[4*e+hV]   / (g_den[4*dst+hV]   + 1e-16f);
        float* ag = g_agg + (size_t)dst*160;
        atomicAdd(ag + hA*40 + (l&15), al0*hs0);
        atomicAdd(ag + (2+hA)*40 + (l&15), al1*hs1);
        int vb = hV*40 + 16 + (l&7)*3;
        atomicAdd(ag+vb,   alv*h0);
        atomicAdd(ag+vb+1, alv*h1);
        atomicAdd(ag+vb+2, alv*h2);
        __syncwarp();
    }
}

// ---- output projection + residual: warp per node ----
__global__ void __launch_bounds__(256) k_out(
    const float* __restrict__ node, const float* __restrict__ Wps,
    const float* __restrict__ Wpv, float* __restrict__ out)
{
    int w = (blockIdx.x*blockDim.x + threadIdx.x) >> 5;
    int l = threadIdx.x & 31;
    if (w >= NN) return;
    const float* ag = g_agg + (size_t)w*160;
    float a0 = ag[(l>>4)*40 + (l&15)];
    float a1 = ag[(2+(l>>4))*40 + (l&15)];
    int vb = (l>>3)*40 + 16 + (l&7)*3;
    float vx = ag[vb], vy = ag[vb+1], vz = ag[vb+2];
    float s0 = 0.f, s1 = 0.f;
    for (int c = 0; c < 32; c++) {
        float b = __shfl_sync(~0u, a0, c);
        s0 += b*Wps[c*64+l]; s1 += b*Wps[c*64+32+l];
    }
    for (int c = 0; c < 32; c++) {
        float b = __shfl_sync(~0u, a1, c);
        s0 += b*Wps[(c+32)*64+l]; s1 += b*Wps[(c+32)*64+32+l];
    }
    float o0 = 0.f, o1 = 0.f, o2 = 0.f;
    for (int c = 0; c < 32; c++) {
        float ww = Wpv[c*32+l];
        o0 += __shfl_sync(~0u, vx, c)*ww;
        o1 += __shfl_sync(~0u, vy, c)*ww;
        o2 += __shfl_sync(~0u, vz, c)*ww;
    }
    const float* nr = node + (size_t)w*160;
    float* orow = out + (size_t)w*160;
    orow[l] = nr[l] + s0;
    orow[32+l] = nr[32+l] + s1;
    orow[64+3*l] = nr[64+3*l] + o0;
    orow[65+3*l] = nr[65+3*l] + o1;
    orow[66+3*l] = nr[66+3*l] + o2;
}

extern "C" void kernel_launch(void* const* d_in, const int* in_sizes, int n_in,
                              void* d_out, int out_size) {
    int ei_pos = -1;
    for (int i = 0; i < n_in; i++) if (in_sizes[i] == 2*EE) { ei_pos = i; break; }
    const float* p[25]; int j = 0;
    for (int i = 0; i < n_in; i++) { if (i == ei_pos) continue; p[j++] = (const float*)d_in[i]; }
    const float *node = p[0], *rbf = p[1], *rsh = p[2], *gs = p[3], *bs = p[4], *gv = p[5],
                *WsS = p[6], *WvS = p[7], *WsD = p[8], *WvD = p[9], *Wr = p[10],
                *Wa = p[11], *ad = p[12], *Wval = p[13], *Wvv = p[14], *Wg = p[15],
                *w2ss = p[16], *w2sv = p[17], *w2vs = p[18], *w2v0 = p[19], *w2v1 = p[20],
                *Wvl = p[21], *Wvv2 = p[22], *Wps = p[23], *Wpv = p[24];
    const int* ei = (const int*)d_in[ei_pos];
    float* out = (float*)d_out;

    cudaFuncSetAttribute(k_edge1, cudaFuncAttributeMaxDynamicSharedMemorySize, 12480*4);
    cudaFuncSetAttribute(k_edge2, cudaFuncAttributeMaxDynamicSharedMemorySize, 35808*4);

    k_init<<<256, 256>>>();
    k_node<<<(NN*32 + 255)/256, 256>>>(node, gs, bs, gv, WsS, WvS, WsD, WvD);
    k_edge1<<<296, 512, 12480*4>>>(ei, rbf, rsh, Wr, Wa, ad);
    k_soft<<<(EE*4 + 255)/256, 256>>>(ei);
    k_edge2<<<148, 512, 35808*4>>>(ei, rbf, rsh, Wr, Wval, Wvv, Wg,
                                   w2ss, w2sv, w2vs, w2v0, w2v1, Wvl, Wvv2);
    k_out<<<(NN*32 + 255)/256, 256>>>(node, Wps, Wpv, out);
}

// round 5
// speedup vs baseline: 1.4075x; 1.3571x over previous
#include <cuda_runtime.h>
#include <math.h>

#define NN 20000
#define EE 320000
#define ISQ3 0.57735026918962576f
#define ISQ2 0.70710678118654752f

__device__ float g_Ssrc[NN*64];
__device__ float g_Sdst[NN*64];
__device__ float g_Vsrc[NN*96];   // [n][x*32+c]
__device__ float g_Vdst[NN*96];
__device__ float g_aex[EE*4];
__device__ unsigned int g_amax[NN*4];
__device__ float g_den[NN*4];
__device__ float g_agg[NN*160];   // per node: [h][16 hs + 24 hv]

__device__ __forceinline__ unsigned int fkey(float f) {
    unsigned int u = __float_as_uint(f);
    return (u & 0x80000000u) ? ~u : (u | 0x80000000u);
}
__device__ __forceinline__ float fdec(unsigned int k) {
    return __uint_as_float((k & 0x80000000u) ? (k ^ 0x80000000u) : ~k);
}
__device__ __forceinline__ float sigf(float x) { return 1.0f / (1.0f + expf(-x)); }

__global__ void k_init() {
    int st = gridDim.x * blockDim.x, t = blockIdx.x*blockDim.x + threadIdx.x;
    for (int i = t; i < NN*4; i += st) { g_amax[i] = 0u; g_den[i] = 0.f; }
    for (int i = t; i < NN*160; i += st) g_agg[i] = 0.f;
}

// ---- node norm + 4 linears: one warp per node ----
__global__ void __launch_bounds__(256) k_node(
    const float* __restrict__ node, const float* __restrict__ gs,
    const float* __restrict__ bs, const float* __restrict__ gv,
    const float* __restrict__ WsS, const float* __restrict__ WvS,
    const float* __restrict__ WsD, const float* __restrict__ WvD)
{
    int w = (blockIdx.x*blockDim.x + threadIdx.x) >> 5;
    int l = threadIdx.x & 31;
    if (w >= NN) return;
    const float* row = node + (size_t)w*160;
    float s0 = row[l], s1 = row[32+l];
    float sum = s0 + s1;
    #pragma unroll
    for (int o = 16; o >= 1; o >>= 1) sum += __shfl_xor_sync(~0u, sum, o);
    float mu = sum * (1.f/64.f);
    float d0 = s0-mu, d1 = s1-mu, vs = d0*d0 + d1*d1;
    #pragma unroll
    for (int o = 16; o >= 1; o >>= 1) vs += __shfl_xor_sync(~0u, vs, o);
    float inv = rsqrtf(vs*(1.f/64.f) + 1e-5f);
    float sn0 = d0*inv*gs[l] + bs[l];
    float sn1 = d1*inv*gs[32+l] + bs[32+l];
    float vx = row[64+3*l], vy = row[65+3*l], vz = row[66+3*l];
    float q = vx*vx + vy*vy + vz*vz;
    #pragma unroll
    for (int o = 16; o >= 1; o >>= 1) q += __shfl_xor_sync(~0u, q, o);
    float sc = gv[l] / sqrtf(q*(1.f/32.f) + 1e-5f);
    vx *= sc; vy *= sc; vz *= sc;
    float r0=0,r1=0,t0=0,t1=0;
    for (int c = 0; c < 32; c++) {
        float b = __shfl_sync(~0u, sn0, c);
        r0 += b*WsS[c*64+l]; r1 += b*WsS[c*64+32+l];
        t0 += b*WsD[c*64+l]; t1 += b*WsD[c*64+32+l];
    }
    for (int c = 0; c < 32; c++) {
        float b = __shfl_sync(~0u, sn1, c);
        r0 += b*WsS[(c+32)*64+l]; r1 += b*WsS[(c+32)*64+32+l];
        t0 += b*WsD[(c+32)*64+l]; t1 += b*WsD[(c+32)*64+32+l];
    }
    g_Ssrc[(size_t)w*64+l] = r0; g_Ssrc[(size_t)w*64+32+l] = r1;
    g_Sdst[(size_t)w*64+l] = t0; g_Sdst[(size_t)w*64+32+l] = t1;
    float a0=0,a1=0,a2=0,b0=0,b1=0,b2=0;
    for (int c = 0; c < 32; c++) {
        float wx = __shfl_sync(~0u, vx, c), wy = __shfl_sync(~0u, vy, c), wz = __shfl_sync(~0u, vz, c);
        float ws = WvS[c*32+l], wd = WvD[c*32+l];
        a0 += wx*ws; a1 += wy*ws; a2 += wz*ws;
        b0 += wx*wd; b1 += wy*wd; b2 += wz*wd;
    }
    float* VS = g_Vsrc + (size_t)w*96; float* VD = g_Vdst + (size_t)w*96;
    VS[l] = a0; VS[32+l] = a1; VS[64+l] = a2;
    VD[l] = b0; VD[32+l] = b1; VD[64+l] = b2;
}

// ---- edge pass 1: attention logits + segment max; warp per 2 edges ----
// smem (floats): WrT 224x20 @0 | WaT 64x100 @4480 | Ad 64 @10880 | M1 16x192 @10944
__global__ void __launch_bounds__(512) k_edge1(
    const int* __restrict__ ei, const float* __restrict__ rbf,
    const float* __restrict__ rsh, const float* __restrict__ Wr,
    const float* __restrict__ Wa, const float* __restrict__ ad)
{
    extern __shared__ float sm[];
    float* sWrT = sm; float* sWaT = sm+4480; float* sAd = sm+10880; float* sM1 = sm+10944;
    int tid = threadIdx.x;
    for (int i = tid; i < 3584; i += 512) { int b = i/224, c = i%224; sWrT[c*20+b] = Wr[i]; }
    for (int i = tid; i < 6144; i += 512) { int k = i/64, o = i%64; sWaT[o*100+k] = Wa[i]; }
    if (tid < 64) sAd[tid] = ad[tid];
    __syncthreads();
    int l = tid & 31, wid = tid >> 5;
    float* m0 = sM1 + wid*192;
    float* m1v = m0 + 96;
    int gw = blockIdx.x*16 + wid, tw = gridDim.x*16;
    for (int p = gw; p < EE/2; p += tw) {
        int e0 = 2*p, e1 = 2*p+1;
        int src0 = ei[e0], dst0 = ei[EE+e0];
        int src1 = ei[e1], dst1 = ei[EE+e1];
        float4 ya = *(const float4*)&rsh[4*e0];
        float4 yb = *(const float4*)&rsh[4*e1];
        float rv = (l < 16) ? rbf[16*e0+l] : rbf[16*e1 + (l-16)];
        float rb0[16], rb1[16];
        #pragma unroll
        for (int b = 0; b < 16; b++) {
            rb0[b] = __shfl_sync(~0u, rv, b);
            rb1[b] = __shfl_sync(~0u, rv, 16+b);
        }
        float w00=0.f, w01=0.f, w05=0.f, w10=0.f, w11=0.f, w15=0.f;
        {
            const float4* r0 = (const float4*)&sWrT[l*20];
            const float4* r1 = (const float4*)&sWrT[(l+32)*20];
            const float4* r5 = (const float4*)&sWrT[(l+160)*20];
            #pragma unroll
            for (int q = 0; q < 4; q++) {
                float4 a = r0[q], b = r1[q], c = r5[q];
                w00 += rb0[4*q]*a.x; w00 += rb0[4*q+1]*a.y; w00 += rb0[4*q+2]*a.z; w00 += rb0[4*q+3]*a.w;
                w01 += rb0[4*q]*b.x; w01 += rb0[4*q+1]*b.y; w01 += rb0[4*q+2]*b.z; w01 += rb0[4*q+3]*b.w;
                w05 += rb0[4*q]*c.x; w05 += rb0[4*q+1]*c.y; w05 += rb0[4*q+2]*c.z; w05 += rb0[4*q+3]*c.w;
                w10 += rb1[4*q]*a.x; w10 += rb1[4*q+1]*a.y; w10 += rb1[4*q+2]*a.z; w10 += rb1[4*q+3]*a.w;
                w11 += rb1[4*q]*b.x; w11 += rb1[4*q+1]*b.y; w11 += rb1[4*q+2]*b.z; w11 += rb1[4*q+3]*b.w;
                w15 += rb1[4*q]*c.x; w15 += rb1[4*q+1]*c.y; w15 += rb1[4*q+2]*c.z; w15 += rb1[4*q+3]*c.w;
            }
        }
        {
            float sc0 = g_Ssrc[src0*64+l]    + g_Sdst[dst0*64+l];
            float sc1 = g_Ssrc[src0*64+32+l] + g_Sdst[dst0*64+32+l];
            float vx = g_Vsrc[src0*96+l]    + g_Vdst[dst0*96+l];
            float vy = g_Vsrc[src0*96+32+l] + g_Vdst[dst0*96+32+l];
            float vz = g_Vsrc[src0*96+64+l] + g_Vdst[dst0*96+64+l];
            float a0 = w00*sc0*ya.x, a1 = w01*sc1*ya.x;
            float a2 = w05*(vx*ya.y + vy*ya.z + vz*ya.w)*ISQ3;
            float sd0 = g_Ssrc[src1*64+l]    + g_Sdst[dst1*64+l];
            float sd1 = g_Ssrc[src1*64+32+l] + g_Sdst[dst1*64+32+l];
            float ux = g_Vsrc[src1*96+l]    + g_Vdst[dst1*96+l];
            float uy = g_Vsrc[src1*96+32+l] + g_Vdst[dst1*96+32+l];
            float uz = g_Vsrc[src1*96+64+l] + g_Vdst[dst1*96+64+l];
            float b0 = w10*sd0*yb.x, b1 = w11*sd1*yb.x;
            float b2 = w15*(ux*yb.y + uy*yb.z + uz*yb.w)*ISQ3;
            __syncwarp();
            m0[l] = a0; m0[32+l] = a1; m0[64+l] = a2;
            m1v[l] = b0; m1v[32+l] = b1; m1v[64+l] = b2;
            __syncwarp();
        }
        float aA0 = 0.f, aB0 = 0.f, aA1 = 0.f, aB1 = 0.f;
        {
            const float4* p0 = (const float4*)m0;
            const float4* p1 = (const float4*)m1v;
            const float4* wa = (const float4*)&sWaT[l*100];
            const float4* wb = (const float4*)&sWaT[(32+l)*100];
            #pragma unroll 8
            for (int q = 0; q < 24; q++) {
                float4 a = wa[q], b = wb[q], u = p0[q], v = p1[q];
                aA0 += u.x*a.x; aA0 += u.y*a.y; aA0 += u.z*a.z; aA0 += u.w*a.w;
                aB0 += u.x*b.x; aB0 += u.y*b.y; aB0 += u.z*b.z; aB0 += u.w*b.w;
                aA1 += v.x*a.x; aA1 += v.y*a.y; aA1 += v.z*a.z; aA1 += v.w*a.w;
                aB1 += v.x*b.x; aB1 += v.y*b.y; aB1 += v.z*b.z; aB1 += v.w*b.w;
            }
        }
        aA0 = aA0 > 0.f ? aA0 : 0.2f*aA0;  aB0 = aB0 > 0.f ? aB0 : 0.2f*aB0;
        aA1 = aA1 > 0.f ? aA1 : 0.2f*aA1;  aB1 = aB1 > 0.f ? aB1 : 0.2f*aB1;
        aA0 *= sAd[l]; aB0 *= sAd[32+l];
        aA1 *= sAd[l]; aB1 *= sAd[32+l];
        #pragma unroll
        for (int o = 8; o >= 1; o >>= 1) {
            aA0 += __shfl_xor_sync(~0u, aA0, o, 16);
            aB0 += __shfl_xor_sync(~0u, aB0, o, 16);
            aA1 += __shfl_xor_sync(~0u, aA1, o, 16);
            aB1 += __shfl_xor_sync(~0u, aB1, o, 16);
        }
        if (l == 0) {
            g_aex[4*e0] = aA0; g_aex[4*e0+2] = aB0;
            atomicMax(&g_amax[4*dst0],   fkey(aA0));
            atomicMax(&g_amax[4*dst0+2], fkey(aB0));
            g_aex[4*e1] = aA1; g_aex[4*e1+2] = aB1;
            atomicMax(&g_amax[4*dst1],   fkey(aA1));
            atomicMax(&g_amax[4*dst1+2], fkey(aB1));
        } else if (l == 16) {
            g_aex[4*e0+1] = aA0; g_aex[4*e0+3] = aB0;
            atomicMax(&g_amax[4*dst0+1], fkey(aA0));
            atomicMax(&g_amax[4*dst0+3], fkey(aB0));
            g_aex[4*e1+1] = aA1; g_aex[4*e1+3] = aB1;
            atomicMax(&g_amax[4*dst1+1], fkey(aA1));
            atomicMax(&g_amax[4*dst1+3], fkey(aB1));
        }
        __syncwarp();
    }
}

__global__ void k_soft(const int* __restrict__ ei) {
    int i = blockIdx.x*blockDim.x + threadIdx.x;
    if (i >= EE*4) return;
    int e = i >> 2, h = i & 3;
    int dst = ei[EE+e];
    float am = fdec(g_amax[4*dst+h]);
    if (!isfinite(am)) am = 0.f;
    float ex = expf(g_aex[i] - am);
    g_aex[i] = ex;
    atomicAdd(&g_den[4*dst+h], ex);
}

// ---- edge pass 2: value path + scatter; warp per 2 edges ----
// smem (floats): WrT 224x20 @0 | WvalT 64x100 @4480 | WgT 32x68 @10880 |
//                WvvT 32x132 @13056 | WvlT 64x100 @17280 | Wvv2T 32x132 @23680 |
//                w2 224 @27904 | staging 16x960 @28128  (total 43488 fl = 173952 B)
__global__ void __launch_bounds__(512) k_edge2(
    const int* __restrict__ ei, const float* __restrict__ rbf,
    const float* __restrict__ rsh, const float* __restrict__ Wr,
    const float* __restrict__ Wval, const float* __restrict__ Wvv,
    const float* __restrict__ Wg,
    const float* __restrict__ w2ss, const float* __restrict__ w2sv,
    const float* __restrict__ w2vs, const float* __restrict__ w2v0,
    const float* __restrict__ w2v1,
    const float* __restrict__ Wvl, const float* __restrict__ Wvv2)
{
    extern __shared__ float sm[];
    float* sWrT   = sm;
    float* sWvalT = sm+4480;
    float* sWgT   = sm+10880;
    float* sWvvT  = sm+13056;
    float* sWvlT  = sm+17280;
    float* sWvv2T = sm+23680;
    float* sw2    = sm+27904;
    float* sB     = sm+28128;
    int tid = threadIdx.x;
    for (int i = tid; i < 3584; i += 512) { int b = i/224, c = i%224; sWrT[c*20+b] = Wr[i]; }
    for (int i = tid; i < 6144; i += 512) { int k = i/64, o = i%64; sWvalT[o*100+k] = Wval[i]; sWvlT[o*100+k] = Wvl[i]; }
    for (int i = tid; i < 2048; i += 512) { int k = i/32, o = i%32; sWgT[o*68+k] = Wg[i]; }
    for (int i = tid; i < 4096; i += 512) { int k = i/32, o = i%32; sWvvT[o*132+k] = Wvv[i]; sWvv2T[o*132+k] = Wvv2[i]; }
    if (tid < 64) { sw2[tid] = w2ss[tid]; sw2[64+tid] = w2sv[tid]; }
    if (tid < 32) { sw2[128+tid] = w2vs[tid]; sw2[160+tid] = w2v0[tid]; sw2[192+tid] = w2v1[tid]; }
    __syncthreads();
    int l = tid & 31, wid = tid >> 5;
    float* B0 = sB + wid*960;
    float* C0 = B0 + 96;
    float* B1 = B0 + 480;
    float* C1 = B1 + 96;
    int gw = blockIdx.x*16 + wid, tw = gridDim.x*16;
    for (int p = gw; p < EE/2; p += tw) {
        int e0 = 2*p, e1 = 2*p+1;
        int src0 = ei[e0], dst0 = ei[EE+e0];
        int src1 = ei[e1], dst1 = ei[EE+e1];
        float4 ya = *(const float4*)&rsh[4*e0];
        float4 yb = *(const float4*)&rsh[4*e1];
        float rv = (l < 16) ? rbf[16*e0+l] : rbf[16*e1 + (l-16)];
        float rb0[16], rb1[16];
        #pragma unroll
        for (int b = 0; b < 16; b++) {
            rb0[b] = __shfl_sync(~0u, rv, b);
            rb1[b] = __shfl_sync(~0u, rv, 16+b);
        }
        float w1a[7] = {0,0,0,0,0,0,0};
        float w1b[7] = {0,0,0,0,0,0,0};
        #pragma unroll
        for (int j = 0; j < 7; j++) {
            const float4* wr = (const float4*)&sWrT[(l+32*j)*20];
            #pragma unroll
            for (int q = 0; q < 4; q++) {
                float4 w = wr[q];
                w1a[j] += rb0[4*q]*w.x; w1a[j] += rb0[4*q+1]*w.y;
                w1a[j] += rb0[4*q+2]*w.z; w1a[j] += rb0[4*q+3]*w.w;
                w1b[j] += rb1[4*q]*w.x; w1b[j] += rb1[4*q+1]*w.y;
                w1b[j] += rb1[4*q+2]*w.z; w1b[j] += rb1[4*q+3]*w.w;
            }
        }
        __syncwarp();
        {   // edge0 gather + CG + staging
            float sc0 = g_Ssrc[src0*64+l]    + g_Sdst[dst0*64+l];
            float sc1 = g_Ssrc[src0*64+32+l] + g_Sdst[dst0*64+32+l];
            float vx = g_Vsrc[src0*96+l]    + g_Vdst[dst0*96+l];
            float vy = g_Vsrc[src0*96+32+l] + g_Vdst[dst0*96+32+l];
            float vz = g_Vsrc[src0*96+64+l] + g_Vdst[dst0*96+64+l];
            float cx = vy*ya.w - vz*ya.z, cy = vz*ya.y - vx*ya.w, cz = vx*ya.z - vy*ya.y;
            B0[l] = w1a[0]*sc0*ya.x; B0[32+l] = w1a[1]*sc1*ya.x;
            B0[64+l] = w1a[5]*(vx*ya.y + vy*ya.z + vz*ya.w)*ISQ3;
            C0[l]    = w1a[2]*sc0*ya.y; C0[128+l] = w1a[2]*sc0*ya.z; C0[256+l] = w1a[2]*sc0*ya.w;
            C0[32+l] = w1a[3]*sc1*ya.y; C0[160+l] = w1a[3]*sc1*ya.z; C0[288+l] = w1a[3]*sc1*ya.w;
            C0[64+l] = w1a[4]*vx*ya.x;  C0[192+l] = w1a[4]*vy*ya.x;  C0[320+l] = w1a[4]*vz*ya.x;
            C0[96+l] = w1a[6]*cx*ISQ2;  C0[224+l] = w1a[6]*cy*ISQ2;  C0[352+l] = w1a[6]*cz*ISQ2;
        }
        {   // edge1 gather + CG + staging
            float sc0 = g_Ssrc[src1*64+l]    + g_Sdst[dst1*64+l];
            float sc1 = g_Ssrc[src1*64+32+l] + g_Sdst[dst1*64+32+l];
            float vx = g_Vsrc[src1*96+l]    + g_Vdst[dst1*96+l];
            float vy = g_Vsrc[src1*96+32+l] + g_Vdst[dst1*96+32+l];
            float vz = g_Vsrc[src1*96+64+l] + g_Vdst[dst1*96+64+l];
            float cx = vy*yb.w - vz*yb.z, cy = vz*yb.y - vx*yb.w, cz = vx*yb.z - vy*yb.y;
            B1[l] = w1b[0]*sc0*yb.x; B1[32+l] = w1b[1]*sc1*yb.x;
            B1[64+l] = w1b[5]*(vx*yb.y + vy*yb.z + vz*yb.w)*ISQ3;
            C1[l]    = w1b[2]*sc0*yb.y; C1[128+l] = w1b[2]*sc0*yb.z; C1[256+l] = w1b[2]*sc0*yb.w;
            C1[32+l] = w1b[3]*sc1*yb.y; C1[160+l] = w1b[3]*sc1*yb.z; C1[288+l] = w1b[3]*sc1*yb.w;
            C1[64+l] = w1b[4]*vx*yb.x;  C1[192+l] = w1b[4]*vy*yb.x;  C1[320+l] = w1b[4]*vz*yb.x;
            C1[96+l] = w1b[6]*cx*ISQ2;  C1[224+l] = w1b[6]*cy*ISQ2;  C1[352+l] = w1b[6]*cz*ISQ2;
        }
        __syncwarp();
        float vs00 = 0.f, vs01 = 0.f, vs10 = 0.f, vs11 = 0.f;
        {
            const float4* p0 = (const float4*)B0;
            const float4* p1 = (const float4*)B1;
            const float4* wa = (const float4*)&sWvalT[l*100];
            const float4* wb = (const float4*)&sWvalT[(32+l)*100];
            #pragma unroll 8
            for (int q = 0; q < 24; q++) {
                float4 a = wa[q], b = wb[q], u = p0[q], v = p1[q];
                vs00 += u.x*a.x; vs00 += u.y*a.y; vs00 += u.z*a.z; vs00 += u.w*a.w;
                vs01 += u.x*b.x; vs01 += u.y*b.y; vs01 += u.z*b.z; vs01 += u.w*b.w;
                vs10 += v.x*a.x; vs10 += v.y*a.y; vs10 += v.z*a.z; vs10 += v.w*a.w;
                vs11 += v.x*b.x; vs11 += v.y*b.y; vs11 += v.z*b.z; vs11 += v.w*b.w;
            }
        }
        __syncwarp();
        B0[l] = vs00; B0[32+l] = vs01;
        B1[l] = vs10; B1[32+l] = vs11;
        __syncwarp();
        float ga0 = 0.f, ga1 = 0.f;
        {
            const float4* p0 = (const float4*)B0;
            const float4* p1 = (const float4*)B1;
            const float4* wg = (const float4*)&sWgT[l*68];
            #pragma unroll
            for (int q = 0; q < 16; q++) {
                float4 w = wg[q], u = p0[q], v = p1[q];
                ga0 += u.x*w.x; ga0 += u.y*w.y; ga0 += u.z*w.z; ga0 += u.w*w.w;
                ga1 += v.x*w.x; ga1 += v.y*w.y; ga1 += v.z*w.z; ga1 += v.w*w.w;
            }
        }
        float gate0 = sigf(ga0), gate1 = sigf(ga1);
        float v00 = 0.f, v01 = 0.f, v02 = 0.f, v10 = 0.f, v11 = 0.f, v12 = 0.f;
        {
            const float4* wp = (const float4*)&sWvvT[l*132];
            const float4* x0 = (const float4*)C0;
            const float4* y0p = x0 + 32;
            const float4* z0 = x0 + 64;
            const float4* x1 = (const float4*)C1;
            const float4* y1p = x1 + 32;
            const float4* z1 = x1 + 64;
            #pragma unroll 4
            for (int q = 0; q < 32; q++) {
                float4 w = wp[q];
                float4 a = x0[q], b = y0p[q], c = z0[q];
                v00 += a.x*w.x; v00 += a.y*w.y; v00 += a.z*w.z; v00 += a.w*w.w;
                v01 += b.x*w.x; v01 += b.y*w.y; v01 += b.z*w.z; v01 += b.w*w.w;
                v02 += c.x*w.x; v02 += c.y*w.y; v02 += c.z*w.z; v02 += c.w*w.w;
                float4 d = x1[q], e = y1p[q], f = z1[q];
                v10 += d.x*w.x; v10 += d.y*w.y; v10 += d.z*w.z; v10 += d.w*w.w;
                v11 += e.x*w.x; v11 += e.y*w.y; v11 += e.z*w.z; v11 += e.w*w.w;
                v12 += f.x*w.x; v12 += f.y*w.y; v12 += f.z*w.z; v12 += f.w*w.w;
            }
        }
        v00 *= gate0; v01 *= gate0; v02 *= gate0;
        v10 *= gate1; v11 *= gate1; v12 *= gate1;
        float ss00 = sigf(vs00), ss01 = sigf(vs01);
        float ss10 = sigf(vs10), ss11 = sigf(vs11);
        __syncwarp();
        {   // second CG staging, edge0
            float c2x = v01*ya.w - v02*ya.z, c2y = v02*ya.y - v00*ya.w, c2z = v00*ya.z - v01*ya.y;
            B0[l] = sw2[l]*ss00*ya.x; B0[32+l] = sw2[32+l]*ss01*ya.x;
            B0[64+l] = sw2[160+l]*(v00*ya.y + v01*ya.z + v02*ya.w)*ISQ3;
            C0[l]    = sw2[64+l]*ss00*ya.y; C0[128+l] = sw2[64+l]*ss00*ya.z; C0[256+l] = sw2[64+l]*ss00*ya.w;
            C0[32+l] = sw2[96+l]*ss01*ya.y; C0[160+l] = sw2[96+l]*ss01*ya.z; C0[288+l] = sw2[96+l]*ss01*ya.w;
            C0[64+l] = sw2[128+l]*v00*ya.x; C0[192+l] = sw2[128+l]*v01*ya.x; C0[320+l] = sw2[128+l]*v02*ya.x;
            C0[96+l] = sw2[192+l]*c2x*ISQ2; C0[224+l] = sw2[192+l]*c2y*ISQ2; C0[352+l] = sw2[192+l]*c2z*ISQ2;
        }
        {   // second CG staging, edge1
            float c2x = v11*yb.w - v12*yb.z, c2y = v12*yb.y - v10*yb.w, c2z = v10*yb.z - v11*yb.y;
            B1[l] = sw2[l]*ss10*yb.x; B1[32+l] = sw2[32+l]*ss11*yb.x;
            B1[64+l] = sw2[160+l]*(v10*yb.y + v11*yb.z + v12*yb.w)*ISQ3;
            C1[l]    = sw2[64+l]*ss10*yb.y; C1[128+l] = sw2[64+l]*ss10*yb.z; C1[256+l] = sw2[64+l]*ss10*yb.w;
            C1[32+l] = sw2[96+l]*ss11*yb.y; C1[160+l] = sw2[96+l]*ss11*yb.z; C1[288+l] = sw2[96+l]*ss11*yb.w;
            C1[64+l] = sw2[128+l]*v10*yb.x; C1[192+l] = sw2[128+l]*v11*yb.x; C1[320+l] = sw2[128+l]*v12*yb.x;
            C1[96+l] = sw2[192+l]*c2x*ISQ2; C1[224+l] = sw2[192+l]*c2y*ISQ2; C1[352+l] = sw2[192+l]*c2z*ISQ2;
        }
        __syncwarp();
        float hs00 = 0.f, hs01 = 0.f, hs10 = 0.f, hs11 = 0.f;
        {
            const float4* p0 = (const float4*)B0;
            const float4* p1 = (const float4*)B1;
            const float4* wa = (const float4*)&sWvlT[l*100];
            const float4* wb = (const float4*)&sWvlT[(32+l)*100];
            #pragma unroll 8
            for (int q = 0; q < 24; q++) {
                float4 a = wa[q], b = wb[q], u = p0[q], v = p1[q];
                hs00 += u.x*a.x; hs00 += u.y*a.y; hs00 += u.z*a.z; hs00 += u.w*a.w;
                hs01 += u.x*b.x; hs01 += u.y*b.y; hs01 += u.z*b.z; hs01 += u.w*b.w;
                hs10 += v.x*a.x; hs10 += v.y*a.y; hs10 += v.z*a.z; hs10 += v.w*a.w;
                hs11 += v.x*b.x; hs11 += v.y*b.y; hs11 += v.z*b.z; hs11 += v.w*b.w;
            }
        }
        float h00 = 0.f, h01 = 0.f, h02 = 0.f, h10 = 0.f, h11 = 0.f, h12 = 0.f;
        {
            const float4* wp = (const float4*)&sWvv2T[l*132];
            const float4* x0 = (const float4*)C0;
            const float4* y0p = x0 + 32;
            const float4* z0 = x0 + 64;
            const float4* x1 = (const float4*)C1;
            const float4* y1p = x1 + 32;
            const float4* z1 = x1 + 64;
            #pragma unroll 4
            for (int q = 0; q < 32; q++) {
                float4 w = wp[q];
                float4 a = x0[q], b = y0p[q], c = z0[q];
                h00 += a.x*w.x; h00 += a.y*w.y; h00 += a.z*w.z; h00 += a.w*w.w;
                h01 += b.x*w.x; h01 += b.y*w.y; h01 += b.z*w.z; h01 += b.w*w.w;
                h02 += c.x*w.x; h02 += c.y*w.y; h02 += c.z*w.z; h02 += c.w*w.w;
                float4 d = x1[q], e = y1p[q], f = z1[q];
                h10 += d.x*w.x; h10 += d.y*w.y; h10 += d.z*w.z; h10 += d.w*w.w;
                h11 += e.x*w.x; h11 += e.y*w.y; h11 += e.z*w.z; h11 += e.w*w.w;
                h12 += f.x*w.x; h12 += f.y*w.y; h12 += f.z*w.z; h12 += f.w*w.w;
            }
        }
        int hA = l >> 4, hV = l >> 3;
        {
            float al0 = g_aex[4*e0+hA]   / (g_den[4*dst0+hA]   + 1e-16f);
            float al1 = g_aex[4*e0+2+hA] / (g_den[4*dst0+2+hA] + 1e-16f);
            float alv = g_aex[4*e0+hV]   / (g_den[4*dst0+hV]   + 1e-16f);
            float* ag = g_agg + (size_t)dst0*160;
            atomicAdd(ag + hA*40 + (l&15), al0*hs00);
            atomicAdd(ag + (2+hA)*40 + (l&15), al1*hs01);
            int vb = hV*40 + 16 + (l&7)*3;
            atomicAdd(ag+vb,   alv*h00);
            atomicAdd(ag+vb+1, alv*h01);
            atomicAdd(ag+vb+2, alv*h02);
        }
        {
            float al0 = g_aex[4*e1+hA]   / (g_den[4*dst1+hA]   + 1e-16f);
            float al1 = g_aex[4*e1+2+hA] / (g_den[4*dst1+2+hA] + 1e-16f);
            float alv = g_aex[4*e1+hV]   / (g_den[4*dst1+hV]   + 1e-16f);
            float* ag = g_agg + (size_t)dst1*160;
            atomicAdd(ag + hA*40 + (l&15), al0*hs10);
            atomicAdd(ag + (2+hA)*40 + (l&15), al1*hs11);
            int vb = hV*40 + 16 + (l&7)*3;
            atomicAdd(ag+vb,   alv*h10);
            atomicAdd(ag+vb+1, alv*h11);
            atomicAdd(ag+vb+2, alv*h12);
        }
        __syncwarp();
    }
}

// ---- output projection + residual: warp per node ----
__global__ void __launch_bounds__(256) k_out(
    const float* __restrict__ node, const float* __restrict__ Wps,
    const float* __restrict__ Wpv, float* __restrict__ out)
{
    int w = (blockIdx.x*blockDim.x + threadIdx.x) >> 5;
    int l = threadIdx.x & 31;
    if (w >= NN) return;
    const float* ag = g_agg + (size_t)w*160;
    float a0 = ag[(l>>4)*40 + (l&15)];
    float a1 = ag[(2+(l>>4))*40 + (l&15)];
    int vb = (l>>3)*40 + 16 + (l&7)*3;
    float vx = ag[vb], vy = ag[vb+1], vz = ag[vb+2];
    float s0 = 0.f, s1 = 0.f;
    for (int c = 0; c < 32; c++) {
        float b = __shfl_sync(~0u, a0, c);
        s0 += b*Wps[c*64+l]; s1 += b*Wps[c*64+32+l];
    }
    for (int c = 0; c < 32; c++) {
        float b = __shfl_sync(~0u, a1, c);
        s0 += b*Wps[(c+32)*64+l]; s1 += b*Wps[(c+32)*64+32+l];
    }
    float o0 = 0.f, o1 = 0.f, o2 = 0.f;
    for (int c = 0; c < 32; c++) {
        float ww = Wpv[c*32+l];
        o0 += __shfl_sync(~0u, vx, c)*ww;
        o1 += __shfl_sync(~0u, vy, c)*ww;
        o2 += __shfl_sync(~0u, vz, c)*ww;
    }
    const float* nr = node + (size_t)w*160;
    float* orow = out + (size_t)w*160;
    orow[l] = nr[l] + s0;
    orow[32+l] = nr[32+l] + s1;
    orow[64+3*l] = nr[64+3*l] + o0;
    orow[65+3*l] = nr[65+3*l] + o1;
    orow[66+3*l] = nr[66+3*l] + o2;
}

extern "C" void kernel_launch(void* const* d_in, const int* in_sizes, int n_in,
                              void* d_out, int out_size) {
    int ei_pos = -1;
    for (int i = 0; i < n_in; i++) if (in_sizes[i] == 2*EE) { ei_pos = i; break; }
    const float* p[25]; int j = 0;
    for (int i = 0; i < n_in; i++) { if (i == ei_pos) continue; p[j++] = (const float*)d_in[i]; }
    const float *node = p[0], *rbf = p[1], *rsh = p[2], *gs = p[3], *bs = p[4], *gv = p[5],
                *WsS = p[6], *WvS = p[7], *WsD = p[8], *WvD = p[9], *Wr = p[10],
                *Wa = p[11], *ad = p[12], *Wval = p[13], *Wvv = p[14], *Wg = p[15],
                *w2ss = p[16], *w2sv = p[17], *w2vs = p[18], *w2v0 = p[19], *w2v1 = p[20],
                *Wvl = p[21], *Wvv2 = p[22], *Wps = p[23], *Wpv = p[24];
    const int* ei = (const int*)d_in[ei_pos];
    float* out = (float*)d_out;

    cudaFuncSetAttribute(k_edge1, cudaFuncAttributeMaxDynamicSharedMemorySize, 14016*4);
    cudaFuncSetAttribute(k_edge2, cudaFuncAttributeMaxDynamicSharedMemorySize, 43488*4);

    k_init<<<256, 256>>>();
    k_node<<<(NN*32 + 255)/256, 256>>>(node, gs, bs, gv, WsS, WvS, WsD, WvD);
    k_edge1<<<296, 512, 14016*4>>>(ei, rbf, rsh, Wr, Wa, ad);
    k_soft<<<(EE*4 + 255)/256, 256>>>(ei);
    k_edge2<<<148, 512, 43488*4>>>(ei, rbf, rsh, Wr, Wval, Wvv, Wg,
                                   w2ss, w2sv, w2vs, w2v0, w2v1, Wvl, Wvv2);
    k_out<<<(NN*32 + 255)/256, 256>>>(node, Wps, Wpv, out);
}

// round 8
// speedup vs baseline: 1.5532x; 1.1035x over previous
#include <cuda_runtime.h>
#include <math.h>

#define NN 20000
#define EE 320000
#define ISQ3 0.57735026918962576f
#define ISQ2 0.70710678118654752f

typedef unsigned long long u64;

__device__ float g_Ssrc[NN*64];
__device__ float g_Sdst[NN*64];
__device__ float g_Vsrc[NN*96];   // [n][x*32+c]
__device__ float g_Vdst[NN*96];
__device__ float g_aex[EE*4];
__device__ unsigned int g_amax[NN*4];
__device__ float g_den[NN*4];
__device__ float g_agg[NN*160];   // per node: [h][16 hs + 24 hv]

__device__ __forceinline__ unsigned int fkey(float f) {
    unsigned int u = __float_as_uint(f);
    return (u & 0x80000000u) ? ~u : (u | 0x80000000u);
}
__device__ __forceinline__ float fdec(unsigned int k) {
    return __uint_as_float((k & 0x80000000u) ? (k ^ 0x80000000u) : ~k);
}
__device__ __forceinline__ float sigf(float x) { return 1.0f / (1.0f + expf(-x)); }

__device__ __forceinline__ u64 pack2(float a, float b) {
    u64 r; asm("mov.b64 %0,{%1,%2};" : "=l"(r) : "f"(a), "f"(b)); return r;
}
__device__ __forceinline__ u64 fma2(u64 a, u64 b, u64 c) {
    u64 d; asm("fma.rn.f32x2 %0,%1,%2,%3;" : "=l"(d) : "l"(a), "l"(b), "l"(c)); return d;
}
__device__ __forceinline__ void unpack2(u64 p, float& a, float& b) {
    asm("mov.b64 {%0,%1},%2;" : "=f"(a), "=f"(b) : "l"(p));
}

__global__ void k_init() {
    int st = gridDim.x * blockDim.x, t = blockIdx.x*blockDim.x + threadIdx.x;
    for (int i = t; i < NN*4; i += st) { g_amax[i] = 0u; g_den[i] = 0.f; }
    for (int i = t; i < NN*160; i += st) g_agg[i] = 0.f;
}

// ---- node norm + 4 linears: one warp per node ----
__global__ void __launch_bounds__(256) k_node(
    const float* __restrict__ node, const float* __restrict__ gs,
    const float* __restrict__ bs, const float* __restrict__ gv,
    const float* __restrict__ WsS, const float* __restrict__ WvS,
    const float* __restrict__ WsD, const float* __restrict__ WvD)
{
    int w = (blockIdx.x*blockDim.x + threadIdx.x) >> 5;
    int l = threadIdx.x & 31;
    if (w >= NN) return;
    const float* row = node + (size_t)w*160;
    float s0 = row[l], s1 = row[32+l];
    float sum = s0 + s1;
    #pragma unroll
    for (int o = 16; o >= 1; o >>= 1) sum += __shfl_xor_sync(~0u, sum, o);
    float mu = sum * (1.f/64.f);
    float d0 = s0-mu, d1 = s1-mu, vs = d0*d0 + d1*d1;
    #pragma unroll
    for (int o = 16; o >= 1; o >>= 1) vs += __shfl_xor_sync(~0u, vs, o);
    float inv = rsqrtf(vs*(1.f/64.f) + 1e-5f);
    float sn0 = d0*inv*gs[l] + bs[l];
    float sn1 = d1*inv*gs[32+l] + bs[32+l];
    float vx = row[64+3*l], vy = row[65+3*l], vz = row[66+3*l];
    float q = vx*vx + vy*vy + vz*vz;
    #pragma unroll
    for (int o = 16; o >= 1; o >>= 1) q += __shfl_xor_sync(~0u, q, o);
    float sc = gv[l] / sqrtf(q*(1.f/32.f) + 1e-5f);
    vx *= sc; vy *= sc; vz *= sc;
    float r0=0,r1=0,t0=0,t1=0;
    for (int c = 0; c < 32; c++) {
        float b = __shfl_sync(~0u, sn0, c);
        r0 += b*WsS[c*64+l]; r1 += b*WsS[c*64+32+l];
        t0 += b*WsD[c*64+l]; t1 += b*WsD[c*64+32+l];
    }
    for (int c = 0; c < 32; c++) {
        float b = __shfl_sync(~0u, sn1, c);
        r0 += b*WsS[(c+32)*64+l]; r1 += b*WsS[(c+32)*64+32+l];
        t0 += b*WsD[(c+32)*64+l]; t1 += b*WsD[(c+32)*64+32+l];
    }
    g_Ssrc[(size_t)w*64+l] = r0; g_Ssrc[(size_t)w*64+32+l] = r1;
    g_Sdst[(size_t)w*64+l] = t0; g_Sdst[(size_t)w*64+32+l] = t1;
    float a0=0,a1=0,a2=0,b0=0,b1=0,b2=0;
    for (int c = 0; c < 32; c++) {
        float wx = __shfl_sync(~0u, vx, c), wy = __shfl_sync(~0u, vy, c), wz = __shfl_sync(~0u, vz, c);
        float ws = WvS[c*32+l], wd = WvD[c*32+l];
        a0 += wx*ws; a1 += wy*ws; a2 += wz*ws;
        b0 += wx*wd; b1 += wy*wd; b2 += wz*wd;
    }
    float* VS = g_Vsrc + (size_t)w*96; float* VD = g_Vdst + (size_t)w*96;
    VS[l] = a0; VS[32+l] = a1; VS[64+l] = a2;
    VD[l] = b0; VD[32+l] = b1; VD[64+l] = b2;
}

#define E1STEP(cc,kk){ \
  float f0=__shfl_sync(~0u,rv0,(kk)), f1=__shfl_sync(~0u,rv0,16+(kk)); \
  float f2=__shfl_sync(~0u,rv1,(kk)), f3=__shfl_sync(~0u,rv1,16+(kk)); \
  wA[0]+=f0*a.cc; wA[1]+=f1*a.cc; wA[2]+=f2*a.cc; wA[3]+=f3*a.cc; \
  wB[0]+=f0*b.cc; wB[1]+=f1*b.cc; wB[2]+=f2*b.cc; wB[3]+=f3*b.cc; \
  wC[0]+=f0*c.cc; wC[1]+=f1*c.cc; wC[2]+=f2*c.cc; wC[3]+=f3*c.cc; }

// ---- edge pass 1: attention logits + segment max; warp per 4 edges ----
// smem (fl): WrT 224x20 @0 | WaP 32x196 @4480 | Ad 64 @10752 | staging 16x768 @10816
__global__ void __launch_bounds__(512) k_edge1(
    const int* __restrict__ ei, const float* __restrict__ rbf,
    const float* __restrict__ rsh, const float* __restrict__ Wr,
    const float* __restrict__ Wa, const float* __restrict__ ad)
{
    extern __shared__ float sm[];
    float* sWrT = sm; float* sWaP = sm+4480; float* sAd = sm+10752; float* sM = sm+10816;
    int tid = threadIdx.x;
    for (int i = tid; i < 3584; i += 512) { int b = i/224, c = i%224; sWrT[c*20+b] = Wr[i]; }
    for (int i = tid; i < 6144; i += 512) {
        int k = i/64, o = i%64;
        if (o < 32) sWaP[o*196 + 2*k] = Wa[i]; else sWaP[(o-32)*196 + 2*k + 1] = Wa[i];
    }
    if (tid < 64) sAd[tid] = ad[tid];
    __syncthreads();
    int l = tid & 31, wid = tid >> 5;
    float* mbase = sM + wid*768;
    int gw = blockIdx.x*16 + wid, tw = gridDim.x*16;
    for (int p = gw; p < EE/4; p += tw) {
        int e0 = 4*p;
        int src[4], dst[4]; float4 Y[4];
        #pragma unroll
        for (int u = 0; u < 4; u++) {
            src[u] = ei[e0+u]; dst[u] = ei[EE+e0+u];
            Y[u] = *(const float4*)&rsh[4*(e0+u)];
        }
        float rv0 = rbf[16*e0 + l], rv1 = rbf[16*e0 + 32 + l];
        float wA[4] = {0,0,0,0}, wB[4] = {0,0,0,0}, wC[4] = {0,0,0,0};
        #pragma unroll
        for (int q = 0; q < 4; q++) {
            float4 a = *(const float4*)&sWrT[l*20 + 4*q];
            float4 b = *(const float4*)&sWrT[(l+32)*20 + 4*q];
            float4 c = *(const float4*)&sWrT[(l+160)*20 + 4*q];
            E1STEP(x, 4*q) E1STEP(y, 4*q+1) E1STEP(z, 4*q+2) E1STEP(w, 4*q+3)
        }
        __syncwarp();
        #pragma unroll
        for (int u = 0; u < 4; u++) {
            float sc0 = g_Ssrc[src[u]*64+l]    + g_Sdst[dst[u]*64+l];
            float sc1 = g_Ssrc[src[u]*64+32+l] + g_Sdst[dst[u]*64+32+l];
            float vx = g_Vsrc[src[u]*96+l]    + g_Vdst[dst[u]*96+l];
            float vy = g_Vsrc[src[u]*96+32+l] + g_Vdst[dst[u]*96+32+l];
            float vz = g_Vsrc[src[u]*96+64+l] + g_Vdst[dst[u]*96+64+l];
            float ms0 = wA[u]*sc0*Y[u].x, ms1 = wB[u]*sc1*Y[u].x;
            float ms2 = wC[u]*(vx*Y[u].y + vy*Y[u].z + vz*Y[u].w)*ISQ3;
            float2* B = (float2*)(mbase + u*192);
            B[l] = make_float2(ms0, ms0); B[32+l] = make_float2(ms1, ms1); B[64+l] = make_float2(ms2, ms2);
        }
        __syncwarp();
        u64 acc0 = 0, acc1 = 0, acc2 = 0, acc3 = 0;
        const ulonglong2* wp = (const ulonglong2*)&sWaP[l*196];
        const ulonglong2* m0 = (const ulonglong2*)(mbase);
        const ulonglong2* m1 = (const ulonglong2*)(mbase+192);
        const ulonglong2* m2 = (const ulonglong2*)(mbase+384);
        const ulonglong2* m3 = (const ulonglong2*)(mbase+576);
        #pragma unroll 8
        for (int j = 0; j < 48; j++) {
            ulonglong2 w2 = wp[j];
            ulonglong2 a = m0[j], b = m1[j], c = m2[j], d = m3[j];
            acc0 = fma2(a.x, w2.x, acc0); acc0 = fma2(a.y, w2.y, acc0);
            acc1 = fma2(b.x, w2.x, acc1); acc1 = fma2(b.y, w2.y, acc1);
            acc2 = fma2(c.x, w2.x, acc2); acc2 = fma2(c.y, w2.y, acc2);
            acc3 = fma2(d.x, w2.x, acc3); acc3 = fma2(d.y, w2.y, acc3);
        }
        float aA[4], aB[4];
        unpack2(acc0, aA[0], aB[0]); unpack2(acc1, aA[1], aB[1]);
        unpack2(acc2, aA[2], aB[2]); unpack2(acc3, aA[3], aB[3]);
        #pragma unroll
        for (int u = 0; u < 4; u++) {
            aA[u] = aA[u] > 0.f ? aA[u] : 0.2f*aA[u];
            aB[u] = aB[u] > 0.f ? aB[u] : 0.2f*aB[u];
            aA[u] *= sAd[l]; aB[u] *= sAd[32+l];
        }
        #pragma unroll
        for (int o = 8; o >= 1; o >>= 1) {
            #pragma unroll
            for (int u = 0; u < 4; u++) {
                aA[u] += __shfl_xor_sync(~0u, aA[u], o, 16);
                aB[u] += __shfl_xor_sync(~0u, aB[u], o, 16);
            }
        }
        if (l == 0) {
            #pragma unroll
            for (int u = 0; u < 4; u++) {
                int e = e0+u, d = dst[u];
                g_aex[4*e] = aA[u]; g_aex[4*e+2] = aB[u];
                atomicMax(&g_amax[4*d],   fkey(aA[u]));
                atomicMax(&g_amax[4*d+2], fkey(aB[u]));
            }
        } else if (l == 16) {
            #pragma unroll
            for (int u = 0; u < 4; u++) {
                int e = e0+u, d = dst[u];
                g_aex[4*e+1] = aA[u]; g_aex[4*e+3] = aB[u];
                atomicMax(&g_amax[4*d+1], fkey(aA[u]));
                atomicMax(&g_amax[4*d+3], fkey(aB[u]));
            }
        }
    }
}

__global__ void k_soft(const int* __restrict__ ei) {
    int i = blockIdx.x*blockDim.x + threadIdx.x;
    if (i >= EE*4) return;
    int e = i >> 2, h = i & 3;
    int dst = ei[EE+e];
    float am = fdec(g_amax[4*dst+h]);
    if (!isfinite(am)) am = 0.f;
    float ex = expf(g_aex[i] - am);
    g_aex[i] = ex;
    atomicAdd(&g_den[4*dst+h], ex);
}

#define E2STEP(cc,kk){ \
  float f0=__shfl_sync(~0u,rv0,(kk)), f1=__shfl_sync(~0u,rv0,16+(kk)); \
  float f2=__shfl_sync(~0u,rv1,(kk)), f3=__shfl_sync(~0u,rv1,16+(kk)); \
  w1[0][0]+=f0*A0.cc; w1[0][1]+=f1*A0.cc; w1[0][2]+=f2*A0.cc; w1[0][3]+=f3*A0.cc; \
  w1[1][0]+=f0*A1.cc; w1[1][1]+=f1*A1.cc; w1[1][2]+=f2*A1.cc; w1[1][3]+=f3*A1.cc; \
  w1[2][0]+=f0*A2.cc; w1[2][1]+=f1*A2.cc; w1[2][2]+=f2*A2.cc; w1[2][3]+=f3*A2.cc; \
  w1[3][0]+=f0*A3.cc; w1[3][1]+=f1*A3.cc; w1[3][2]+=f2*A3.cc; w1[3][3]+=f3*A3.cc; \
  w1[4][0]+=f0*A4.cc; w1[4][1]+=f1*A4.cc; w1[4][2]+=f2*A4.cc; w1[4][3]+=f3*A4.cc; \
  w1[5][0]+=f0*A5.cc; w1[5][1]+=f1*A5.cc; w1[5][2]+=f2*A5.cc; w1[5][3]+=f3*A5.cc; \
  w1[6][0]+=f0*A6.cc; w1[6][1]+=f1*A6.cc; w1[6][2]+=f2*A6.cc; w1[6][3]+=f3*A6.cc; }

// ---- edge pass 2: value path + scatter; 384 thr, warp per 4 edges ----
// smem (fl): WrT 4480 | WvalP 32x196 @4480 | WgT 32x68 @10752 | WvvT 32x132 @12928 |
//            WvlP 32x196 @17152 | Wvv2T 32x132 @23424 | w2 224 @27648 | staging 12x2304 @27872
//            total 55520 fl = 222080 B
__global__ void __launch_bounds__(384) k_edge2(
    const int* __restrict__ ei, const float* __restrict__ rbf,
    const float* __restrict__ rsh, const float* __restrict__ Wr,
    const float* __restrict__ Wval, const float* __restrict__ Wvv,
    const float* __restrict__ Wg,
    const float* __restrict__ w2ss, const float* __restrict__ w2sv,
    const float* __restrict__ w2vs, const float* __restrict__ w2v0,
    const float* __restrict__ w2v1,
    const float* __restrict__ Wvl, const float* __restrict__ Wvv2)
{
    extern __shared__ float sm[];
    float* sWrT   = sm;
    float* sWvalP = sm+4480;
    float* sWgT   = sm+10752;
    float* sWvvT  = sm+12928;
    float* sWvlP  = sm+17152;
    float* sWvv2T = sm+23424;
    float* sw2    = sm+27648;
    float* sB     = sm+27872;
    int tid = threadIdx.x;
    for (int i = tid; i < 3584; i += 384) { int b = i/224, c = i%224; sWrT[c*20+b] = Wr[i]; }
    for (int i = tid; i < 6144; i += 384) {
        int k = i/64, o = i%64;
        if (o < 32) { sWvalP[o*196+2*k] = Wval[i]; sWvlP[o*196+2*k] = Wvl[i]; }
        else { sWvalP[(o-32)*196+2*k+1] = Wval[i]; sWvlP[(o-32)*196+2*k+1] = Wvl[i]; }
    }
    for (int i = tid; i < 2048; i += 384) { int k = i/32, o = i%32; sWgT[o*68+k] = Wg[i]; }
    for (int i = tid; i < 4096; i += 384) { int k = i/32, o = i%32; sWvvT[o*132+k] = Wvv[i]; sWvv2T[o*132+k] = Wvv2[i]; }
    if (tid < 64) { sw2[tid] = w2ss[tid]; sw2[64+tid] = w2sv[tid]; }
    if (tid < 32) { sw2[128+tid] = w2vs[tid]; sw2[160+tid] = w2v0[tid]; sw2[192+tid] = w2v1[tid]; }
    __syncthreads();
    int l = tid & 31, wid = tid >> 5;   // wid 0..11
    float* ebase = sB + wid*2304;       // per edge u: B=+u*576 (192), Cxy=+192 (256), Cz=+448 (128)
    int gw = blockIdx.x*12 + wid, tw = gridDim.x*12;
    for (int p = gw; p < EE/4; p += tw) {
        int e0 = 4*p;
        int src[4], dst[4]; float4 Y[4];
        #pragma unroll
        for (int u = 0; u < 4; u++) {
            src[u] = ei[e0+u]; dst[u] = ei[EE+e0+u];
            Y[u] = *(const float4*)&rsh[4*(e0+u)];
        }
        float rv0 = rbf[16*e0 + l], rv1 = rbf[16*e0 + 32 + l];
        float w1[7][4];
        #pragma unroll
        for (int j = 0; j < 7; j++) { w1[j][0]=0.f; w1[j][1]=0.f; w1[j][2]=0.f; w1[j][3]=0.f; }
        #pragma unroll
        for (int q = 0; q < 4; q++) {
            float4 A0 = *(const float4*)&sWrT[(l      )*20 + 4*q];
            float4 A1 = *(const float4*)&sWrT[(l + 32 )*20 + 4*q];
            float4 A2 = *(const float4*)&sWrT[(l + 64 )*20 + 4*q];
            float4 A3 = *(const float4*)&sWrT[(l + 96 )*20 + 4*q];
            float4 A4 = *(const float4*)&sWrT[(l + 128)*20 + 4*q];
            float4 A5 = *(const float4*)&sWrT[(l + 160)*20 + 4*q];
            float4 A6 = *(const float4*)&sWrT[(l + 192)*20 + 4*q];
            E2STEP(x, 4*q) E2STEP(y, 4*q+1) E2STEP(z, 4*q+2) E2STEP(w, 4*q+3)
        }
        __syncwarp();
        #pragma unroll
        for (int u = 0; u < 4; u++) {
            float4 Yu = Y[u];
            float sc0 = g_Ssrc[src[u]*64+l]    + g_Sdst[dst[u]*64+l];
            float sc1 = g_Ssrc[src[u]*64+32+l] + g_Sdst[dst[u]*64+32+l];
            float vx = g_Vsrc[src[u]*96+l]    + g_Vdst[dst[u]*96+l];
            float vy = g_Vsrc[src[u]*96+32+l] + g_Vdst[dst[u]*96+32+l];
            float vz = g_Vsrc[src[u]*96+64+l] + g_Vdst[dst[u]*96+64+l];
            float cx = vy*Yu.w - vz*Yu.z, cy = vz*Yu.y - vx*Yu.w, cz = vx*Yu.z - vy*Yu.y;
            float ms0 = w1[0][u]*sc0*Yu.x, ms1 = w1[1][u]*sc1*Yu.x;
            float ms2 = w1[5][u]*(vx*Yu.y + vy*Yu.z + vz*Yu.w)*ISQ3;
            float2* B = (float2*)(ebase + u*576);
            float2* Cxy = (float2*)(ebase + u*576 + 192);
            float* Cz = ebase + u*576 + 448;
            B[l] = make_float2(ms0, ms0); B[32+l] = make_float2(ms1, ms1); B[64+l] = make_float2(ms2, ms2);
            float g2 = w1[2][u]*sc0, g3 = w1[3][u]*sc1, g4 = w1[4][u], g6 = w1[6][u]*ISQ2;
            Cxy[l]    = make_float2(g2*Yu.y, g2*Yu.z);       Cz[l]    = g2*Yu.w;
            Cxy[32+l] = make_float2(g3*Yu.y, g3*Yu.z);       Cz[32+l] = g3*Yu.w;
            Cxy[64+l] = make_float2(g4*vx*Yu.x, g4*vy*Yu.x); Cz[64+l] = g4*vz*Yu.x;
            Cxy[96+l] = make_float2(g6*cx, g6*cy);           Cz[96+l] = g6*cz;
        }
        __syncwarp();
        // val_s: packed outputs {l, 32+l}
        float vs0[4], vs1[4];
        {
            u64 a0 = 0, a1 = 0, a2 = 0, a3 = 0;
            const ulonglong2* wp = (const ulonglong2*)&sWvalP[l*196];
            const ulonglong2* m0 = (const ulonglong2*)(ebase);
            const ulonglong2* m1 = (const ulonglong2*)(ebase+576);
            const ulonglong2* m2 = (const ulonglong2*)(ebase+1152);
            const ulonglong2* m3 = (const ulonglong2*)(ebase+1728);
            #pragma unroll 8
            for (int j = 0; j < 48; j++) {
                ulonglong2 w2 = wp[j];
                ulonglong2 a = m0[j], b = m1[j], c = m2[j], d = m3[j];
                a0 = fma2(a.x, w2.x, a0); a0 = fma2(a.y, w2.y, a0);
                a1 = fma2(b.x, w2.x, a1); a1 = fma2(b.y, w2.y, a1);
                a2 = fma2(c.x, w2.x, a2); a2 = fma2(c.y, w2.y, a2);
                a3 = fma2(d.x, w2.x, a3); a3 = fma2(d.y, w2.y, a3);
            }
            unpack2(a0, vs0[0], vs1[0]); unpack2(a1, vs0[1], vs1[1]);
            unpack2(a2, vs0[2], vs1[2]); unpack2(a3, vs0[3], vs1[3]);
        }
        __syncwarp();
        #pragma unroll
        for (int u = 0; u < 4; u++) {
            float2* B = (float2*)(ebase + u*576);
            B[l] = make_float2(vs0[u], vs0[u]); B[32+l] = make_float2(vs1[u], vs1[u]);
        }
        __syncwarp();
        // gate (scalar weights, dup'd messages: use .x/.z)
        float gate[4];
        {
            float ga[4] = {0,0,0,0};
            const float4* wg = (const float4*)&sWgT[l*68];
            #pragma unroll 4
            for (int j = 0; j < 16; j++) {
                float4 w = wg[j];
                #pragma unroll
                for (int u = 0; u < 4; u++) {
                    const float4* mb = (const float4*)(ebase + u*576);
                    float4 mA = mb[2*j], mB = mb[2*j+1];
                    ga[u] += mA.x*w.x; ga[u] += mA.z*w.y; ga[u] += mB.x*w.z; ga[u] += mB.z*w.w;
                }
            }
            #pragma unroll
            for (int u = 0; u < 4; u++) gate[u] = sigf(ga[u]);
        }
        // val_v: packed x,y comps; z scalar
        float v0[4], v1[4], v2[4];
        {
            u64 axy[4] = {0,0,0,0}; float az[4] = {0,0,0,0};
            const float4* wv = (const float4*)&sWvvT[l*132];
            #pragma unroll 4
            for (int j = 0; j < 32; j++) {
                float4 w = wv[j];
                u64 wd0 = pack2(w.x, w.x), wd1 = pack2(w.y, w.y);
                u64 wd2 = pack2(w.z, w.z), wd3 = pack2(w.w, w.w);
                #pragma unroll
                for (int u = 0; u < 4; u++) {
                    const ulonglong2* cxy = (const ulonglong2*)(ebase + u*576 + 192);
                    const float4* cz = (const float4*)(ebase + u*576 + 448);
                    ulonglong2 cA = cxy[2*j], cB = cxy[2*j+1];
                    float4 z = cz[j];
                    axy[u] = fma2(cA.x, wd0, axy[u]); axy[u] = fma2(cA.y, wd1, axy[u]);
                    axy[u] = fma2(cB.x, wd2, axy[u]); axy[u] = fma2(cB.y, wd3, axy[u]);
                    az[u] += z.x*w.x; az[u] += z.y*w.y; az[u] += z.z*w.z; az[u] += z.w*w.w;
                }
            }
            #pragma unroll
            for (int u = 0; u < 4; u++) { unpack2(axy[u], v0[u], v1[u]); v2[u] = az[u]; }
        }
        #pragma unroll
        for (int u = 0; u < 4; u++) { v0[u] *= gate[u]; v1[u] *= gate[u]; v2[u] *= gate[u]; }
        __syncwarp();
        #pragma unroll
        for (int u = 0; u < 4; u++) {
            float4 Yu = Y[u];
            float ss0 = sigf(vs0[u]), ss1 = sigf(vs1[u]);
            float c2x = v1[u]*Yu.w - v2[u]*Yu.z, c2y = v2[u]*Yu.y - v0[u]*Yu.w, c2z = v0[u]*Yu.z - v1[u]*Yu.y;
            float2* B = (float2*)(ebase + u*576);
            float2* Cxy = (float2*)(ebase + u*576 + 192);
            float* Cz = ebase + u*576 + 448;
            float n0 = sw2[l]*ss0*Yu.x, n1 = sw2[32+l]*ss1*Yu.x;
            float n2 = sw2[160+l]*(v0[u]*Yu.y + v1[u]*Yu.z + v2[u]*Yu.w)*ISQ3;
            B[l] = make_float2(n0, n0); B[32+l] = make_float2(n1, n1); B[64+l] = make_float2(n2, n2);
            float g2 = sw2[64+l]*ss0, g3 = sw2[96+l]*ss1, g4 = sw2[128+l], g6 = sw2[192+l]*ISQ2;
            Cxy[l]    = make_float2(g2*Yu.y, g2*Yu.z);             Cz[l]    = g2*Yu.w;
            Cxy[32+l] = make_float2(g3*Yu.y, g3*Yu.z);             Cz[32+l] = g3*Yu.w;
            Cxy[64+l] = make_float2(g4*v0[u]*Yu.x, g4*v1[u]*Yu.x); Cz[64+l] = g4*v2[u]*Yu.x;
            Cxy[96+l] = make_float2(g6*c2x, g6*c2y);               Cz[96+l] = g6*c2z;
        }
        __syncwarp();
        // hs: packed outputs
        float hsA[4], hsB[4];
        {
            u64 a0 = 0, a1 = 0, a2 = 0, a3 = 0;
            const ulonglong2* wp = (const ulonglong2*)&sWvlP[l*196];
            const ulonglong2* m0 = (const ulonglong2*)(ebase);
            const ulonglong2* m1 = (const ulonglong2*)(ebase+576);
            const ulonglong2* m2 = (const ulonglong2*)(ebase+1152);
            const ulonglong2* m3 = (const ulonglong2*)(ebase+1728);
            #pragma unroll 8
            for (int j = 0; j < 48; j++) {
                ulonglong2 w2 = wp[j];
                ulonglong2 a = m0[j], b = m1[j], c = m2[j], d = m3[j];
                a0 = fma2(a.x, w2.x, a0); a0 = fma2(a.y, w2.y, a0);
                a1 = fma2(b.x, w2.x, a1); a1 = fma2(b.y, w2.y, a1);
                a2 = fma2(c.x, w2.x, a2); a2 = fma2(c.y, w2.y, a2);
                a3 = fma2(d.x, w2.x, a3); a3 = fma2(d.y, w2.y, a3);
            }
            unpack2(a0, hsA[0], hsB[0]); unpack2(a1, hsA[1], hsB[1]);
            unpack2(a2, hsA[2], hsB[2]); unpack2(a3, hsA[3], hsB[3]);
        }
        // hv: packed x,y; z scalar
        float h0[4], h1[4], h2[4];
        {
            u64 axy[4] = {0,0,0,0}; float az[4] = {0,0,0,0};
            const float4* wv = (const float4*)&sWvv2T[l*132];
            #pragma unroll 4
            for (int j = 0; j < 32; j++) {
                float4 w = wv[j];
                u64 wd0 = pack2(w.x, w.x), wd1 = pack2(w.y, w.y);
                u64 wd2 = pack2(w.z, w.z), wd3 = pack2(w.w, w.w);
                #pragma unroll
                for (int u = 0; u < 4; u++) {
                    const ulonglong2* cxy = (const ulonglong2*)(ebase + u*576 + 192);
                    const float4* cz = (const float4*)(ebase + u*576 + 448);
                    ulonglong2 cA = cxy[2*j], cB = cxy[2*j+1];
                    float4 z = cz[j];
                    axy[u] = fma2(cA.x, wd0, axy[u]); axy[u] = fma2(cA.y, wd1, axy[u]);
                    axy[u] = fma2(cB.x, wd2, axy[u]); axy[u] = fma2(cB.y, wd3, axy[u]);
                    az[u] += z.x*w.x; az[u] += z.y*w.y; az[u] += z.z*w.z; az[u] += z.w*w.w;
                }
            }
            #pragma unroll
            for (int u = 0; u < 4; u++) { unpack2(axy[u], h0[u], h1[u]); h2[u] = az[u]; }
        }
        // attention weights & scatter
        int hA = l >> 4, hV = l >> 3;
        #pragma unroll
        for (int u = 0; u < 4; u++) {
            int e = e0+u, d = dst[u];
            float al0 = g_aex[4*e+hA]   / (g_den[4*d+hA]   + 1e-16f);
            float al1 = g_aex[4*e+2+hA] / (g_den[4*d+2+hA] + 1e-16f);
            float alv = g_aex[4*e+hV]   / (g_den[4*d+hV]   + 1e-16f);
            float* ag = g_agg + (size_t)d*160;
            atomicAdd(ag + hA*40 + (l&15), al0*hsA[u]);
            atomicAdd(ag + (2+hA)*40 + (l&15), al1*hsB[u]);
            int vb = hV*40 + 16 + (l&7)*3;
            atomicAdd(ag+vb,   alv*h0[u]);
            atomicAdd(ag+vb+1, alv*h1[u]);
            atomicAdd(ag+vb+2, alv*h2[u]);
        }
    }
}

// ---- output projection + residual: warp per node ----
__global__ void __launch_bounds__(256) k_out(
    const float* __restrict__ node, const float* __restrict__ Wps,
    const float* __restrict__ Wpv, float* __restrict__ out)
{
    int w = (blockIdx.x*blockDim.x + threadIdx.x) >> 5;
    int l = threadIdx.x & 31;
    if (w >= NN) return;
    const float* ag = g_agg + (size_t)w*160;
    float a0 = ag[(l>>4)*40 + (l&15)];
    float a1 = ag[(2+(l>>4))*40 + (l&15)];
    int vb = (l>>3)*40 + 16 + (l&7)*3;
    float vx = ag[vb], vy = ag[vb+1], vz = ag[vb+2];
    float s0 = 0.f, s1 = 0.f;
    for (int c = 0; c < 32; c++) {
        float b = __shfl_sync(~0u, a0, c);
        s0 += b*Wps[c*64+l]; s1 += b*Wps[c*64+32+l];
    }
    for (int c = 0; c < 32; c++) {
        float b = __shfl_sync(~0u, a1, c);
        s0 += b*Wps[(c+32)*64+l]; s1 += b*Wps[(c+32)*64+32+l];
    }
    float o0 = 0.f, o1 = 0.f, o2 = 0.f;
    for (int c = 0; c < 32; c++) {
        float ww = Wpv[c*32+l];
        o0 += __shfl_sync(~0u, vx, c)*ww;
        o1 += __shfl_sync(~0u, vy, c)*ww;
        o2 += __shfl_sync(~0u, vz, c)*ww;
    }
    const float* nr = node + (size_t)w*160;
    float* orow = out + (size_t)w*160;
    orow[l] = nr[l] + s0;
    orow[32+l] = nr[32+l] + s1;
    orow[64+3*l] = nr[64+3*l] + o0;
    orow[65+3*l] = nr[65+3*l] + o1;
    orow[66+3*l] = nr[66+3*l] + o2;
}

extern "C" void kernel_launch(void* const* d_in, const int* in_sizes, int n_in,
                              void* d_out, int out_size) {
    int ei_pos = -1;
    for (int i = 0; i < n_in; i++) if (in_sizes[i] == 2*EE) { ei_pos = i; break; }
    const float* p[25]; int j = 0;
    for (int i = 0; i < n_in; i++) { if (i == ei_pos) continue; p[j++] = (const float*)d_in[i]; }
    const float *node = p[0], *rbf = p[1], *rsh = p[2], *gs = p[3], *bs = p[4], *gv = p[5],
                *WsS = p[6], *WvS = p[7], *WsD = p[8], *WvD = p[9], *Wr = p[10],
                *Wa = p[11], *ad = p[12], *Wval = p[13], *Wvv = p[14], *Wg = p[15],
                *w2ss = p[16], *w2sv = p[17], *w2vs = p[18], *w2v0 = p[19], *w2v1 = p[20],
                *Wvl = p[21], *Wvv2 = p[22], *Wps = p[23], *Wpv = p[24];
    const int* ei = (const int*)d_in[ei_pos];
    float* out = (float*)d_out;

    cudaFuncSetAttribute(k_edge1, cudaFuncAttributeMaxDynamicSharedMemorySize, 23104*4);
    cudaFuncSetAttribute(k_edge2, cudaFuncAttributeMaxDynamicSharedMemorySize, 55520*4);

    k_init<<<256, 256>>>();
    k_node<<<(NN*32 + 255)/256, 256>>>(node, gs, bs, gv, WsS, WvS, WsD, WvD);
    k_edge1<<<152, 512, 23104*4>>>(ei, rbf, rsh, Wr, Wa, ad);
    k_soft<<<(EE*4 + 255)/256, 256>>>(ei);
    k_edge2<<<152, 384, 55520*4>>>(ei, rbf, rsh, Wr, Wval, Wvv, Wg,
                                   w2ss, w2sv, w2vs, w2v0, w2v1, Wvl, Wvv2);
    k_out<<<(NN*32 + 255)/256, 256>>>(node, Wps, Wpv, out);
}

// round 10
// speedup vs baseline: 1.6561x; 1.0663x over previous
#include <cuda_runtime.h>
#include <math.h>

#define NN 20000
#define EE 320000
#define ISQ3 0.57735026918962576f
#define ISQ2 0.70710678118654752f

typedef unsigned long long u64;

__device__ float g_Ssrc[NN*64];
__device__ float g_Sdst[NN*64];
__device__ float g_Vsrc[NN*96];   // [n][x*32+c]
__device__ float g_Vdst[NN*96];
__device__ float g_aex[EE*4];
__device__ unsigned int g_amax[NN*4];
__device__ float g_den[NN*4];
__device__ float g_agg[NN*160];   // per node: [h][16 hs + 24 hv]

__device__ __forceinline__ unsigned int fkey(float f) {
    unsigned int u = __float_as_uint(f);
    return (u & 0x80000000u) ? ~u : (u | 0x80000000u);
}
__device__ __forceinline__ float fdec(unsigned int k) {
    return __uint_as_float((k & 0x80000000u) ? (k ^ 0x80000000u) : ~k);
}
__device__ __forceinline__ float sigf(float x) { return 1.0f / (1.0f + expf(-x)); }

__device__ __forceinline__ u64 pack2(float a, float b) {
    u64 r; asm("mov.b64 %0,{%1,%2};" : "=l"(r) : "f"(a), "f"(b)); return r;
}
__device__ __forceinline__ u64 fma2(u64 a, u64 b, u64 c) {
    u64 d; asm("fma.rn.f32x2 %0,%1,%2,%3;" : "=l"(d) : "l"(a), "l"(b), "l"(c)); return d;
}
__device__ __forceinline__ void unpack2(u64 p, float& a, float& b) {
    asm("mov.b64 {%0,%1},%2;" : "=f"(a), "=f"(b) : "l"(p));
}

__global__ void k_init() {
    int st = gridDim.x * blockDim.x, t = blockIdx.x*blockDim.x + threadIdx.x;
    for (int i = t; i < NN*4; i += st) { g_amax[i] = 0u; g_den[i] = 0.f; }
    for (int i = t; i < NN*160; i += st) g_agg[i] = 0.f;
}

// ---- node norm + 4 linears: one warp per node ----
__global__ void __launch_bounds__(256) k_node(
    const float* __restrict__ node, const float* __restrict__ gs,
    const float* __restrict__ bs, const float* __restrict__ gv,
    const float* __restrict__ WsS, const float* __restrict__ WvS,
    const float* __restrict__ WsD, const float* __restrict__ WvD)
{
    int w = (blockIdx.x*blockDim.x + threadIdx.x) >> 5;
    int l = threadIdx.x & 31;
    if (w >= NN) return;
    const float* row = node + (size_t)w*160;
    float s0 = row[l], s1 = row[32+l];
    float sum = s0 + s1;
    #pragma unroll
    for (int o = 16; o >= 1; o >>= 1) sum += __shfl_xor_sync(~0u, sum, o);
    float mu = sum * (1.f/64.f);
    float d0 = s0-mu, d1 = s1-mu, vs = d0*d0 + d1*d1;
    #pragma unroll
    for (int o = 16; o >= 1; o >>= 1) vs += __shfl_xor_sync(~0u, vs, o);
    float inv = rsqrtf(vs*(1.f/64.f) + 1e-5f);
    float sn0 = d0*inv*gs[l] + bs[l];
    float sn1 = d1*inv*gs[32+l] + bs[32+l];
    float vx = row[64+3*l], vy = row[65+3*l], vz = row[66+3*l];
    float q = vx*vx + vy*vy + vz*vz;
    #pragma unroll
    for (int o = 16; o >= 1; o >>= 1) q += __shfl_xor_sync(~0u, q, o);
    float sc = gv[l] / sqrtf(q*(1.f/32.f) + 1e-5f);
    vx *= sc; vy *= sc; vz *= sc;
    float r0=0,r1=0,t0=0,t1=0;
    for (int c = 0; c < 32; c++) {
        float b = __shfl_sync(~0u, sn0, c);
        r0 += b*WsS[c*64+l]; r1 += b*WsS[c*64+32+l];
        t0 += b*WsD[c*64+l]; t1 += b*WsD[c*64+32+l];
    }
    for (int c = 0; c < 32; c++) {
        float b = __shfl_sync(~0u, sn1, c);
        r0 += b*WsS[(c+32)*64+l]; r1 += b*WsS[(c+32)*64+32+l];
        t0 += b*WsD[(c+32)*64+l]; t1 += b*WsD[(c+32)*64+32+l];
    }
    g_Ssrc[(size_t)w*64+l] = r0; g_Ssrc[(size_t)w*64+32+l] = r1;
    g_Sdst[(size_t)w*64+l] = t0; g_Sdst[(size_t)w*64+32+l] = t1;
    float a0=0,a1=0,a2=0,b0=0,b1=0,b2=0;
    for (int c = 0; c < 32; c++) {
        float wx = __shfl_sync(~0u, vx, c), wy = __shfl_sync(~0u, vy, c), wz = __shfl_sync(~0u, vz, c);
        float ws = WvS[c*32+l], wd = WvD[c*32+l];
        a0 += wx*ws; a1 += wy*ws; a2 += wz*ws;
        b0 += wx*wd; b1 += wy*wd; b2 += wz*wd;
    }
    float* VS = g_Vsrc + (size_t)w*96; float* VD = g_Vdst + (size_t)w*96;
    VS[l] = a0; VS[32+l] = a1; VS[64+l] = a2;
    VD[l] = b0; VD[32+l] = b1; VD[64+l] = b2;
}

#define E1STEP(cc,kk){ \
  float f0=__shfl_sync(~0u,rv0,(kk)), f1=__shfl_sync(~0u,rv0,16+(kk)); \
  float f2=__shfl_sync(~0u,rv1,(kk)), f3=__shfl_sync(~0u,rv1,16+(kk)); \
  wA[0]+=f0*a.cc; wA[1]+=f1*a.cc; wA[2]+=f2*a.cc; wA[3]+=f3*a.cc; \
  wB[0]+=f0*b.cc; wB[1]+=f1*b.cc; wB[2]+=f2*b.cc; wB[3]+=f3*b.cc; \
  wC[0]+=f0*c.cc; wC[1]+=f1*c.cc; wC[2]+=f2*c.cc; wC[3]+=f3*c.cc; }

// ---- edge pass 1: attention logits + segment max; warp per 4 edges ----
__global__ void __launch_bounds__(512) k_edge1(
    const int* __restrict__ ei, const float* __restrict__ rbf,
    const float* __restrict__ rsh, const float* __restrict__ Wr,
    const float* __restrict__ Wa, const float* __restrict__ ad)
{
    extern __shared__ float sm[];
    float* sWrT = sm; float* sWaP = sm+4480; float* sAd = sm+10752; float* sM = sm+10816;
    int tid = threadIdx.x;
    for (int i = tid; i < 3584; i += 512) { int b = i/224, c = i%224; sWrT[c*20+b] = Wr[i]; }
    for (int i = tid; i < 6144; i += 512) {
        int k = i/64, o = i%64;
        if (o < 32) sWaP[o*196 + 2*k] = Wa[i]; else sWaP[(o-32)*196 + 2*k + 1] = Wa[i];
    }
    if (tid < 64) sAd[tid] = ad[tid];
    __syncthreads();
    int l = tid & 31, wid = tid >> 5;
    float* mbase = sM + wid*768;
    int gw = blockIdx.x*16 + wid, tw = gridDim.x*16;
    for (int p = gw; p < EE/4; p += tw) {
        int e0 = 4*p;
        int src[4], dst[4]; float4 Y[4];
        #pragma unroll
        for (int u = 0; u < 4; u++) {
            src[u] = ei[e0+u]; dst[u] = ei[EE+e0+u];
            Y[u] = *(const float4*)&rsh[4*(e0+u)];
        }
        float rv0 = rbf[16*e0 + l], rv1 = rbf[16*e0 + 32 + l];
        float wA[4] = {0,0,0,0}, wB[4] = {0,0,0,0}, wC[4] = {0,0,0,0};
        #pragma unroll
        for (int q = 0; q < 4; q++) {
            float4 a = *(const float4*)&sWrT[l*20 + 4*q];
            float4 b = *(const float4*)&sWrT[(l+32)*20 + 4*q];
            float4 c = *(const float4*)&sWrT[(l+160)*20 + 4*q];
            E1STEP(x, 4*q) E1STEP(y, 4*q+1) E1STEP(z, 4*q+2) E1STEP(w, 4*q+3)
        }
        __syncwarp();
        #pragma unroll
        for (int u = 0; u < 4; u++) {
            float sc0 = g_Ssrc[src[u]*64+l]    + g_Sdst[dst[u]*64+l];
            float sc1 = g_Ssrc[src[u]*64+32+l] + g_Sdst[dst[u]*64+32+l];
            float vx = g_Vsrc[src[u]*96+l]    + g_Vdst[dst[u]*96+l];
            float vy = g_Vsrc[src[u]*96+32+l] + g_Vdst[dst[u]*96+32+l];
            float vz = g_Vsrc[src[u]*96+64+l] + g_Vdst[dst[u]*96+64+l];
            float ms0 = wA[u]*sc0*Y[u].x, ms1 = wB[u]*sc1*Y[u].x;
            float ms2 = wC[u]*(vx*Y[u].y + vy*Y[u].z + vz*Y[u].w)*ISQ3;
            float2* B = (float2*)(mbase + u*192);
            B[l] = make_float2(ms0, ms0); B[32+l] = make_float2(ms1, ms1); B[64+l] = make_float2(ms2, ms2);
        }
        __syncwarp();
        u64 acc0 = 0, acc1 = 0, acc2 = 0, acc3 = 0;
        const ulonglong2* wp = (const ulonglong2*)&sWaP[l*196];
        const ulonglong2* m0 = (const ulonglong2*)(mbase);
        const ulonglong2* m1 = (const ulonglong2*)(mbase+192);
        const ulonglong2* m2 = (const ulonglong2*)(mbase+384);
        const ulonglong2* m3 = (const ulonglong2*)(mbase+576);
        #pragma unroll 8
        for (int j = 0; j < 48; j++) {
            ulonglong2 w2 = wp[j];
            ulonglong2 a = m0[j], b = m1[j], c = m2[j], d = m3[j];
            acc0 = fma2(a.x, w2.x, acc0); acc0 = fma2(a.y, w2.y, acc0);
            acc1 = fma2(b.x, w2.x, acc1); acc1 = fma2(b.y, w2.y, acc1);
            acc2 = fma2(c.x, w2.x, acc2); acc2 = fma2(c.y, w2.y, acc2);
            acc3 = fma2(d.x, w2.x, acc3); acc3 = fma2(d.y, w2.y, acc3);
        }
        float aA[4], aB[4];
        unpack2(acc0, aA[0], aB[0]); unpack2(acc1, aA[1], aB[1]);
        unpack2(acc2, aA[2], aB[2]); unpack2(acc3, aA[3], aB[3]);
        #pragma unroll
        for (int u = 0; u < 4; u++) {
            aA[u] = aA[u] > 0.f ? aA[u] : 0.2f*aA[u];
            aB[u] = aB[u] > 0.f ? aB[u] : 0.2f*aB[u];
            aA[u] *= sAd[l]; aB[u] *= sAd[32+l];
        }
        #pragma unroll
        for (int o = 8; o >= 1; o >>= 1) {
            #pragma unroll
            for (int u = 0; u < 4; u++) {
                aA[u] += __shfl_xor_sync(~0u, aA[u], o, 16);
                aB[u] += __shfl_xor_sync(~0u, aB[u], o, 16);
            }
        }
        if (l == 0) {
            #pragma unroll
            for (int u = 0; u < 4; u++) {
                int e = e0+u, d = dst[u];
                g_aex[4*e] = aA[u]; g_aex[4*e+2] = aB[u];
                atomicMax(&g_amax[4*d],   fkey(aA[u]));
                atomicMax(&g_amax[4*d+2], fkey(aB[u]));
            }
        } else if (l == 16) {
            #pragma unroll
            for (int u = 0; u < 4; u++) {
                int e = e0+u, d = dst[u];
                g_aex[4*e+1] = aA[u]; g_aex[4*e+3] = aB[u];
                atomicMax(&g_amax[4*d+1], fkey(aA[u]));
                atomicMax(&g_amax[4*d+3], fkey(aB[u]));
            }
        }
    }
}

__global__ void k_soft(const int* __restrict__ ei) {
    int i = blockIdx.x*blockDim.x + threadIdx.x;
    if (i >= EE*4) return;
    int e = i >> 2, h = i & 3;
    int dst = ei[EE+e];
    float am = fdec(g_amax[4*dst+h]);
    if (!isfinite(am)) am = 0.f;
    float ex = expf(g_aex[i] - am);
    g_aex[i] = ex;
    atomicAdd(&g_den[4*dst+h], ex);
}

// w1 GEMV step: 4 edges, f32x2 over weight-row pairs (j0,j1),(j2,j3),(j4,j6), j5 scalar
#define W1K(cc,kk){ \
  float f0=__shfl_sync(~0u,rv0,(kk)), f1=__shfl_sync(~0u,rv0,16+(kk)); \
  float f2=__shfl_sync(~0u,rv1,(kk)), f3=__shfl_sync(~0u,rv1,16+(kk)); \
  u64 wp01=pack2(A0.cc,A1.cc), wp23=pack2(A2.cc,A3.cc), wp46=pack2(A4.cc,A6.cc); \
  u64 md0=pack2(f0,f0), md1=pack2(f1,f1), md2=pack2(f2,f2), md3=pack2(f3,f3); \
  accw[0][0]=fma2(md0,wp01,accw[0][0]); accw[0][1]=fma2(md0,wp23,accw[0][1]); accw[0][2]=fma2(md0,wp46,accw[0][2]); acc5[0]+=f0*A5.cc; \
  accw[1][0]=fma2(md1,wp01,accw[1][0]); accw[1][1]=fma2(md1,wp23,accw[1][1]); accw[1][2]=fma2(md1,wp46,accw[1][2]); acc5[1]+=f1*A5.cc; \
  accw[2][0]=fma2(md2,wp01,accw[2][0]); accw[2][1]=fma2(md2,wp23,accw[2][1]); accw[2][2]=fma2(md2,wp46,accw[2][2]); acc5[2]+=f2*A5.cc; \
  accw[3][0]=fma2(md3,wp01,accw[3][0]); accw[3][1]=fma2(md3,wp23,accw[3][1]); accw[3][2]=fma2(md3,wp46,accw[3][2]); acc5[3]+=f3*A5.cc; }

// ---- edge pass 2: value path + scatter; 448 thr, warp per 4 edges (2 pairs) ----
// smem (fl): WrT 4480 | WvalT 64x100 @4480 | WgT 32x68 @10880 | WvvT 32x132 @13056 |
//            WvlT 64x100 @17280 | Wvv2T 32x132 @23680 | w2 224 @27904 | staging 14x1920 @28128
//            total 55008 fl = 220032 B
// per-warp staging: 2 pairs x 960 fl: Bpair 192 | Cxy_e0 256 | Cxy_e1 256 | CzPair 256
__global__ void __launch_bounds__(448) k_edge2(
    const int* __restrict__ ei, const float* __restrict__ rbf,
    const float* __restrict__ rsh, const float* __restrict__ Wr,
    const float* __restrict__ Wval, const float* __restrict__ Wvv,
    const float* __restrict__ Wg,
    const float* __restrict__ w2ss, const float* __restrict__ w2sv,
    const float* __restrict__ w2vs, const float* __restrict__ w2v0,
    const float* __restrict__ w2v1,
    const float* __restrict__ Wvl, const float* __restrict__ Wvv2)
{
    extern __shared__ float sm[];
    float* sWrT   = sm;
    float* sWvalT = sm+4480;
    float* sWgT   = sm+10880;
    float* sWvvT  = sm+13056;
    float* sWvlT  = sm+17280;
    float* sWvv2T = sm+23680;
    float* sw2    = sm+27904;
    float* sB     = sm+28128;
    int tid = threadIdx.x;
    for (int i = tid; i < 3584; i += 448) { int b = i/224, c = i%224; sWrT[c*20+b] = Wr[i]; }
    for (int i = tid; i < 6144; i += 448) { int k = i/64, o = i%64; sWvalT[o*100+k] = Wval[i]; sWvlT[o*100+k] = Wvl[i]; }
    for (int i = tid; i < 2048; i += 448) { int k = i/32, o = i%32; sWgT[o*68+k] = Wg[i]; }
    for (int i = tid; i < 4096; i += 448) { int k = i/32, o = i%32; sWvvT[o*132+k] = Wvv[i]; sWvv2T[o*132+k] = Wvv2[i]; }
    if (tid < 64) { sw2[tid] = w2ss[tid]; sw2[64+tid] = w2sv[tid]; }
    if (tid < 32) { sw2[128+tid] = w2vs[tid]; sw2[160+tid] = w2v0[tid]; sw2[192+tid] = w2v1[tid]; }
    __syncthreads();
    int l = tid & 31, wid = tid >> 5;   // wid 0..13
    float* ebase = sB + wid*1920;
    int gw = blockIdx.x*14 + wid, tw = gridDim.x*14;
    for (int p = gw; p < EE/4; p += tw) {
        int e0 = 4*p;
        int src[4], dst[4]; float4 Y[4];
        #pragma unroll
        for (int u = 0; u < 4; u++) {
            src[u] = ei[e0+u]; dst[u] = ei[EE+e0+u];
            Y[u] = *(const float4*)&rsh[4*(e0+u)];
        }
        float rv0 = rbf[16*e0 + l], rv1 = rbf[16*e0 + 32 + l];
        // ---- w1 = rbf @ Wrbf (paired f32x2) ----
        u64 accw[4][3]; float acc5[4];
        #pragma unroll
        for (int u = 0; u < 4; u++) { accw[u][0]=0; accw[u][1]=0; accw[u][2]=0; acc5[u]=0.f; }
        #pragma unroll
        for (int q = 0; q < 4; q++) {
            float4 A0 = *(const float4*)&sWrT[(l      )*20 + 4*q];
            float4 A1 = *(const float4*)&sWrT[(l + 32 )*20 + 4*q];
            float4 A2 = *(const float4*)&sWrT[(l + 64 )*20 + 4*q];
            float4 A3 = *(const float4*)&sWrT[(l + 96 )*20 + 4*q];
            float4 A4 = *(const float4*)&sWrT[(l + 128)*20 + 4*q];
            float4 A5 = *(const float4*)&sWrT[(l + 160)*20 + 4*q];
            float4 A6 = *(const float4*)&sWrT[(l + 192)*20 + 4*q];
            W1K(x, 4*q) W1K(y, 4*q+1) W1K(z, 4*q+2) W1K(w, 4*q+3)
        }
        float w1[7][4];
        #pragma unroll
        for (int u = 0; u < 4; u++) {
            unpack2(accw[u][0], w1[0][u], w1[1][u]);
            unpack2(accw[u][1], w1[2][u], w1[3][u]);
            unpack2(accw[u][2], w1[4][u], w1[6][u]);
            w1[5][u] = acc5[u];
        }
        __syncwarp();
        // ---- stage 1: gather + CG product ----
        #pragma unroll
        for (int pr = 0; pr < 2; pr++) {
            int u0 = 2*pr, u1 = u0+1;
            float* pb = ebase + pr*960;
            float2* Bp  = (float2*)pb;
            float2* Cx0 = (float2*)(pb+192);
            float2* Cx1 = (float2*)(pb+448);
            float2* Czp = (float2*)(pb+704);
            float4 Ya = Y[u0], Yb = Y[u1];
            float sa0 = g_Ssrc[src[u0]*64+l]    + g_Sdst[dst[u0]*64+l];
            float sa1 = g_Ssrc[src[u0]*64+32+l] + g_Sdst[dst[u0]*64+32+l];
            float ax = g_Vsrc[src[u0]*96+l]    + g_Vdst[dst[u0]*96+l];
            float ay = g_Vsrc[src[u0]*96+32+l] + g_Vdst[dst[u0]*96+32+l];
            float az = g_Vsrc[src[u0]*96+64+l] + g_Vdst[dst[u0]*96+64+l];
            float sb0 = g_Ssrc[src[u1]*64+l]    + g_Sdst[dst[u1]*64+l];
            float sb1 = g_Ssrc[src[u1]*64+32+l] + g_Sdst[dst[u1]*64+32+l];
            float bx = g_Vsrc[src[u1]*96+l]    + g_Vdst[dst[u1]*96+l];
            float by = g_Vsrc[src[u1]*96+32+l] + g_Vdst[dst[u1]*96+32+l];
            float bz = g_Vsrc[src[u1]*96+64+l] + g_Vdst[dst[u1]*96+64+l];
            float cax = ay*Ya.w - az*Ya.z, cay = az*Ya.y - ax*Ya.w, caz = ax*Ya.z - ay*Ya.y;
            float cbx = by*Yb.w - bz*Yb.z, cby = bz*Yb.y - bx*Yb.w, cbz = bx*Yb.z - by*Yb.y;
            Bp[l]    = make_float2(w1[0][u0]*sa0*Ya.x, w1[0][u1]*sb0*Yb.x);
            Bp[32+l] = make_float2(w1[1][u0]*sa1*Ya.x, w1[1][u1]*sb1*Yb.x);
            Bp[64+l] = make_float2(w1[5][u0]*(ax*Ya.y+ay*Ya.z+az*Ya.w)*ISQ3,
                                   w1[5][u1]*(bx*Yb.y+by*Yb.z+bz*Yb.w)*ISQ3);
            float g2a = w1[2][u0]*sa0, g3a = w1[3][u0]*sa1, g4a = w1[4][u0], g6a = w1[6][u0]*ISQ2;
            float g2b = w1[2][u1]*sb0, g3b = w1[3][u1]*sb1, g4b = w1[4][u1], g6b = w1[6][u1]*ISQ2;
            Cx0[l]    = make_float2(g2a*Ya.y, g2a*Ya.z);
            Cx0[32+l] = make_float2(g3a*Ya.y, g3a*Ya.z);
            Cx0[64+l] = make_float2(g4a*ax*Ya.x, g4a*ay*Ya.x);
            Cx0[96+l] = make_float2(g6a*cax, g6a*cay);
            Cx1[l]    = make_float2(g2b*Yb.y, g2b*Yb.z);
            Cx1[32+l] = make_float2(g3b*Yb.y, g3b*Yb.z);
            Cx1[64+l] = make_float2(g4b*bx*Yb.x, g4b*by*Yb.x);
            Cx1[96+l] = make_float2(g6b*cbx, g6b*cby);
            Czp[l]    = make_float2(g2a*Ya.w,      g2b*Yb.w);
            Czp[32+l] = make_float2(g3a*Ya.w,      g3b*Yb.w);
            Czp[64+l] = make_float2(g4a*az*Ya.x,   g4b*bz*Yb.x);
            Czp[96+l] = make_float2(g6a*caz,       g6b*cbz);
        }
        __syncwarp();
        const ulonglong2* mp0 = (const ulonglong2*)(ebase);
        const ulonglong2* mp1 = (const ulonglong2*)(ebase+960);
        // ---- val_s (pre-sigmoid): paired edges, 2 output rows ----
        float vs0[4], vs1[4];
        {
            u64 aA0=0, aB0=0, aA1=0, aB1=0;
            const float4* wa = (const float4*)&sWvalT[l*100];
            const float4* wb = (const float4*)&sWvalT[(32+l)*100];
            #pragma unroll 6
            for (int j = 0; j < 24; j++) {
                float4 a = wa[j], b = wb[j];
                ulonglong2 mA0 = mp0[2*j], mB0 = mp0[2*j+1];
                ulonglong2 mA1 = mp1[2*j], mB1 = mp1[2*j+1];
                u64 p0=pack2(a.x,a.x), p1=pack2(a.y,a.y), p2=pack2(a.z,a.z), p3=pack2(a.w,a.w);
                u64 q0=pack2(b.x,b.x), q1=pack2(b.y,b.y), q2=pack2(b.z,b.z), q3=pack2(b.w,b.w);
                aA0 = fma2(mA0.x,p0,aA0); aA0 = fma2(mA0.y,p1,aA0); aA0 = fma2(mB0.x,p2,aA0); aA0 = fma2(mB0.y,p3,aA0);
                aB0 = fma2(mA0.x,q0,aB0); aB0 = fma2(mA0.y,q1,aB0); aB0 = fma2(mB0.x,q2,aB0); aB0 = fma2(mB0.y,q3,aB0);
                aA1 = fma2(mA1.x,p0,aA1); aA1 = fma2(mA1.y,p1,aA1); aA1 = fma2(mB1.x,p2,aA1); aA1 = fma2(mB1.y,p3,aA1);
                aB1 = fma2(mA1.x,q0,aB1); aB1 = fma2(mA1.y,q1,aB1); aB1 = fma2(mB1.x,q2,aB1); aB1 = fma2(mB1.y,q3,aB1);
            }
            unpack2(aA0, vs0[0], vs0[1]); unpack2(aB0, vs1[0], vs1[1]);
            unpack2(aA1, vs0[2], vs0[3]); unpack2(aB1, vs1[2], vs1[3]);
        }
        __syncwarp();
        ((float2*)ebase)[l]        = make_float2(vs0[0], vs0[1]);
        ((float2*)ebase)[32+l]     = make_float2(vs1[0], vs1[1]);
        ((float2*)(ebase+960))[l]    = make_float2(vs0[2], vs0[3]);
        ((float2*)(ebase+960))[32+l] = make_float2(vs1[2], vs1[3]);
        __syncwarp();
        // ---- gate ----
        float gate[4];
        {
            u64 aG0 = 0, aG1 = 0;
            const float4* wg = (const float4*)&sWgT[l*68];
            #pragma unroll 4
            for (int j = 0; j < 16; j++) {
                float4 w = wg[j];
                ulonglong2 mA0 = mp0[2*j], mB0 = mp0[2*j+1];
                ulonglong2 mA1 = mp1[2*j], mB1 = mp1[2*j+1];
                u64 p0=pack2(w.x,w.x), p1=pack2(w.y,w.y), p2=pack2(w.z,w.z), p3=pack2(w.w,w.w);
                aG0 = fma2(mA0.x,p0,aG0); aG0 = fma2(mA0.y,p1,aG0); aG0 = fma2(mB0.x,p2,aG0); aG0 = fma2(mB0.y,p3,aG0);
                aG1 = fma2(mA1.x,p0,aG1); aG1 = fma2(mA1.y,p1,aG1); aG1 = fma2(mB1.x,p2,aG1); aG1 = fma2(mB1.y,p3,aG1);
            }
            float gE0,gE1,gE2,gE3;
            unpack2(aG0,gE0,gE1); unpack2(aG1,gE2,gE3);
            gate[0]=sigf(gE0); gate[1]=sigf(gE1); gate[2]=sigf(gE2); gate[3]=sigf(gE3);
        }
        // ---- val_v: xy packed per edge, z packed per pair ----
        float v0[4], v1[4], v2[4];
        {
            u64 axy[4] = {0,0,0,0}; u64 az0 = 0, az1 = 0;
            const float4* wv = (const float4*)&sWvvT[l*132];
            const ulonglong2* cxA = (const ulonglong2*)(ebase+192);
            const ulonglong2* cxB = (const ulonglong2*)(ebase+448);
            const ulonglong2* cxC = (const ulonglong2*)(ebase+960+192);
            const ulonglong2* cxD = (const ulonglong2*)(ebase+960+448);
            const ulonglong2* czA = (const ulonglong2*)(ebase+704);
            const ulonglong2* czB = (const ulonglong2*)(ebase+960+704);
            #pragma unroll 4
            for (int j = 0; j < 32; j++) {
                float4 w = wv[j];
                u64 p0=pack2(w.x,w.x), p1=pack2(w.y,w.y), p2=pack2(w.z,w.z), p3=pack2(w.w,w.w);
                ulonglong2 a0 = cxA[2*j], a1 = cxA[2*j+1];
                axy[0] = fma2(a0.x,p0,axy[0]); axy[0] = fma2(a0.y,p1,axy[0]);
                axy[0] = fma2(a1.x,p2,axy[0]); axy[0] = fma2(a1.y,p3,axy[0]);
                ulonglong2 b0 = cxB[2*j], b1 = cxB[2*j+1];
                axy[1] = fma2(b0.x,p0,axy[1]); axy[1] = fma2(b0.y,p1,axy[1]);
                axy[1] = fma2(b1.x,p2,axy[1]); axy[1] = fma2(b1.y,p3,axy[1]);
                ulonglong2 c0 = cxC[2*j], c1 = cxC[2*j+1];
                axy[2] = fma2(c0.x,p0,axy[2]); axy[2] = fma2(c0.y,p1,axy[2]);
                axy[2] = fma2(c1.x,p2,axy[2]); axy[2] = fma2(c1.y,p3,axy[2]);
                ulonglong2 d0 = cxD[2*j], d1 = cxD[2*j+1];
                axy[3] = fma2(d0.x,p0,axy[3]); axy[3] = fma2(d0.y,p1,axy[3]);
                axy[3] = fma2(d1.x,p2,axy[3]); axy[3] = fma2(d1.y,p3,axy[3]);
                ulonglong2 z0 = czA[2*j], z1 = czA[2*j+1];
                az0 = fma2(z0.x,p0,az0); az0 = fma2(z0.y,p1,az0);
                az0 = fma2(z1.x,p2,az0); az0 = fma2(z1.y,p3,az0);
                ulonglong2 z2 = czB[2*j], z3 = czB[2*j+1];
                az1 = fma2(z2.x,p0,az1); az1 = fma2(z2.y,p1,az1);
                az1 = fma2(z3.x,p2,az1); az1 = fma2(z3.y,p3,az1);
            }
            #pragma unroll
            for (int u = 0; u < 4; u++) unpack2(axy[u], v0[u], v1[u]);
            unpack2(az0, v2[0], v2[1]); unpack2(az1, v2[2], v2[3]);
        }
        #pragma unroll
        for (int u = 0; u < 4; u++) { v0[u] *= gate[u]; v1[u] *= gate[u]; v2[u] *= gate[u]; }
        __syncwarp();
        // ---- stage 2: second CG product ----
        #pragma unroll
        for (int pr = 0; pr < 2; pr++) {
            int u0 = 2*pr, u1 = u0+1;
            float* pb = ebase + pr*960;
            float2* Bp  = (float2*)pb;
            float2* Cx0 = (float2*)(pb+192);
            float2* Cx1 = (float2*)(pb+448);
            float2* Czp = (float2*)(pb+704);
            float4 Ya = Y[u0], Yb = Y[u1];
            float ssa = sigf(vs0[u0]), sta = sigf(vs1[u0]);
            float ssb = sigf(vs0[u1]), stb = sigf(vs1[u1]);
            float cax = v1[u0]*Ya.w - v2[u0]*Ya.z, cay = v2[u0]*Ya.y - v0[u0]*Ya.w, caz = v0[u0]*Ya.z - v1[u0]*Ya.y;
            float cbx = v1[u1]*Yb.w - v2[u1]*Yb.z, cby = v2[u1]*Yb.y - v0[u1]*Yb.w, cbz = v0[u1]*Yb.z - v1[u1]*Yb.y;
            Bp[l]    = make_float2(sw2[l]*ssa*Ya.x, sw2[l]*ssb*Yb.x);
            Bp[32+l] = make_float2(sw2[32+l]*sta*Ya.x, sw2[32+l]*stb*Yb.x);
            Bp[64+l] = make_float2(sw2[160+l]*(v0[u0]*Ya.y+v1[u0]*Ya.z+v2[u0]*Ya.w)*ISQ3,
                                   sw2[160+l]*(v0[u1]*Yb.y+v1[u1]*Yb.z+v2[u1]*Yb.w)*ISQ3);
            float g2a = sw2[64+l]*ssa, g3a = sw2[96+l]*sta, g4 = sw2[128+l], g6 = sw2[192+l]*ISQ2;
            float g2b = sw2[64+l]*ssb, g3b = sw2[96+l]*stb;
            Cx0[l]    = make_float2(g2a*Ya.y, g2a*Ya.z);
            Cx0[32+l] = make_float2(g3a*Ya.y, g3a*Ya.z);
            Cx0[64+l] = make_float2(g4*v0[u0]*Ya.x, g4*v1[u0]*Ya.x);
            Cx0[96+l] = make_float2(g6*cax, g6*cay);
            Cx1[l]    = make_float2(g2b*Yb.y, g2b*Yb.z);
            Cx1[32+l] = make_float2(g3b*Yb.y, g3b*Yb.z);
            Cx1[64+l] = make_float2(g4*v0[u1]*Yb.x, g4*v1[u1]*Yb.x);
            Cx1[96+l] = make_float2(g6*cbx, g6*cby);
            Czp[l]    = make_float2(g2a*Ya.w,        g2b*Yb.w);
            Czp[32+l] = make_float2(g3a*Ya.w,        g3b*Yb.w);
            Czp[64+l] = make_float2(g4*v2[u0]*Ya.x,  g4*v2[u1]*Yb.x);
            Czp[96+l] = make_float2(g6*caz,          g6*cbz);
        }
        __syncwarp();
        // ---- hs ----
        float hsA[4], hsB[4];
        {
            u64 aA0=0, aB0=0, aA1=0, aB1=0;
            const float4* wa = (const float4*)&sWvlT[l*100];
            const float4* wb = (const float4*)&sWvlT[(32+l)*100];
            #pragma unroll 6
            for (int j = 0; j < 24; j++) {
                float4 a = wa[j], b = wb[j];
                ulonglong2 mA0 = mp0[2*j], mB0 = mp0[2*j+1];
                ulonglong2 mA1 = mp1[2*j], mB1 = mp1[2*j+1];
                u64 p0=pack2(a.x,a.x), p1=pack2(a.y,a.y), p2=pack2(a.z,a.z), p3=pack2(a.w,a.w);
                u64 q0=pack2(b.x,b.x), q1=pack2(b.y,b.y), q2=pack2(b.z,b.z), q3=pack2(b.w,b.w);
                aA0 = fma2(mA0.x,p0,aA0); aA0 = fma2(mA0.y,p1,aA0); aA0 = fma2(mB0.x,p2,aA0); aA0 = fma2(mB0.y,p3,aA0);
                aB0 = fma2(mA0.x,q0,aB0); aB0 = fma2(mA0.y,q1,aB0); aB0 = fma2(mB0.x,q2,aB0); aB0 = fma2(mB0.y,q3,aB0);
                aA1 = fma2(mA1.x,p0,aA1); aA1 = fma2(mA1.y,p1,aA1); aA1 = fma2(mB1.x,p2,aA1); aA1 = fma2(mB1.y,p3,aA1);
                aB1 = fma2(mA1.x,q0,aB1); aB1 = fma2(mA1.y,q1,aB1); aB1 = fma2(mB1.x,q2,aB1); aB1 = fma2(mB1.y,q3,aB1);
            }
            unpack2(aA0, hsA[0], hsA[1]); unpack2(aB0, hsB[0], hsB[1]);
            unpack2(aA1, hsA[2], hsA[3]); unpack2(aB1, hsB[2], hsB[3]);
        }
        // ---- hv ----
        float h0[4], h1[4], h2[4];
        {
            u64 axy[4] = {0,0,0,0}; u64 az0 = 0, az1 = 0;
            const float4* wv = (const float4*)&sWvv2T[l*132];
            const ulonglong2* cxA = (const ulonglong2*)(ebase+192);
            const ulonglong2* cxB = (const ulonglong2*)(ebase+448);
            const ulonglong2* cxC = (const ulonglong2*)(ebase+960+192);
            const ulonglong2* cxD = (const ulonglong2*)(ebase+960+448);
            const ulonglong2* czA = (const ulonglong2*)(ebase+704);
            const ulonglong2* czB = (const ulonglong2*)(ebase+960+704);
            #pragma unroll 4
            for (int j = 0; j < 32; j++) {
                float4 w = wv[j];
                u64 p0=pack2(w.x,w.x), p1=pack2(w.y,w.y), p2=pack2(w.z,w.z), p3=pack2(w.w,w.w);
                ulonglong2 a0 = cxA[2*j], a1 = cxA[2*j+1];
                axy[0] = fma2(a0.x,p0,axy[0]); axy[0] = fma2(a0.y,p1,axy[0]);
                axy[0] = fma2(a1.x,p2,axy[0]); axy[0] = fma2(a1.y,p3,axy[0]);
                ulonglong2 b0 = cxB[2*j], b1 = cxB[2*j+1];
                axy[1] = fma2(b0.x,p0,axy[1]); axy[1] = fma2(b0.y,p1,axy[1]);
                axy[1] = fma2(b1.x,p2,axy[1]); axy[1] = fma2(b1.y,p3,axy[1]);
                ulonglong2 c0 = cxC[2*j], c1 = cxC[2*j+1];
                axy[2] = fma2(c0.x,p0,axy[2]); axy[2] = fma2(c0.y,p1,axy[2]);
                axy[2] = fma2(c1.x,p2,axy[2]); axy[2] = fma2(c1.y,p3,axy[2]);
                ulonglong2 d0 = cxD[2*j], d1 = cxD[2*j+1];
                axy[3] = fma2(d0.x,p0,axy[3]); axy[3] = fma2(d0.y,p1,axy[3]);
                axy[3] = fma2(d1.x,p2,axy[3]); axy[3] = fma2(d1.y,p3,axy[3]);
                ulonglong2 z0 = czA[2*j], z1 = czA[2*j+1];
                az0 = fma2(z0.x,p0,az0); az0 = fma2(z0.y,p1,az0);
                az0 = fma2(z1.x,p2,az0); az0 = fma2(z1.y,p3,az0);
                ulonglong2 z2 = czB[2*j], z3 = czB[2*j+1];
                az1 = fma2(z2.x,p0,az1); az1 = fma2(z2.y,p1,az1);
                az1 = fma2(z3.x,p2,az1); az1 = fma2(z3.y,p3,az1);
            }
            #pragma unroll
            for (int u = 0; u < 4; u++) unpack2(axy[u], h0[u], h1[u]);
            unpack2(az0, h2[0], h2[1]); unpack2(az1, h2[2], h2[3]);
        }
        // ---- attention weights & scatter ----
        int hA = l >> 4, hV = l >> 3;
        #pragma unroll
        for (int u = 0; u < 4; u++) {
            int e = e0+u, d = dst[u];
            float al0 = g_aex[4*e+hA]   / (g_den[4*d+hA]   + 1e-16f);
            float al1 = g_aex[4*e+2+hA] / (g_den[4*d+2+hA] + 1e-16f);
            float alv = g_aex[4*e+hV]   / (g_den[4*d+hV]   + 1e-16f);
            float* ag = g_agg + (size_t)d*160;
            atomicAdd(ag + hA*40 + (l&15), al0*hsA[u]);
            atomicAdd(ag + (2+hA)*40 + (l&15), al1*hsB[u]);
            int vb = hV*40 + 16 + (l&7)*3;
            atomicAdd(ag+vb,   alv*h0[u]);
            atomicAdd(ag+vb+1, alv*h1[u]);
            atomicAdd(ag+vb+2, alv*h2[u]);
        }
        __syncwarp();
    }
}

// ---- output projection + residual: warp per node ----
__global__ void __launch_bounds__(256) k_out(
    const float* __restrict__ node, const float* __restrict__ Wps,
    const float* __restrict__ Wpv, float* __restrict__ out)
{
    int w = (blockIdx.x*blockDim.x + threadIdx.x) >> 5;
    int l = threadIdx.x & 31;
    if (w >= NN) return;
    const float* ag = g_agg + (size_t)w*160;
    float a0 = ag[(l>>4)*40 + (l&15)];
    float a1 = ag[(2+(l>>4))*40 + (l&15)];
    int vb = (l>>3)*40 + 16 + (l&7)*3;
    float vx = ag[vb], vy = ag[vb+1], vz = ag[vb+2];
    float s0 = 0.f, s1 = 0.f;
    for (int c = 0; c < 32; c++) {
        float b = __shfl_sync(~0u, a0, c);
        s0 += b*Wps[c*64+l]; s1 += b*Wps[c*64+32+l];
    }
    for (int c = 0; c < 32; c++) {
        float b = __shfl_sync(~0u, a1, c);
        s0 += b*Wps[(c+32)*64+l]; s1 += b*Wps[(c+32)*64+32+l];
    }
    float o0 = 0.f, o1 = 0.f, o2 = 0.f;
    for (int c = 0; c < 32; c++) {
        float ww = Wpv[c*32+l];
        o0 += __shfl_sync(~0u, vx, c)*ww;
        o1 += __shfl_sync(~0u, vy, c)*ww;
        o2 += __shfl_sync(~0u, vz, c)*ww;
    }
    const float* nr = node + (size_t)w*160;
    float* orow = out + (size_t)w*160;
    orow[l] = nr[l] + s0;
    orow[32+l] = nr[32+l] + s1;
    orow[64+3*l] = nr[64+3*l] + o0;
    orow[65+3*l] = nr[65+3*l] + o1;
    orow[66+3*l] = nr[66+3*l] + o2;
}

extern "C" void kernel_launch(void* const* d_in, const int* in_sizes, int n_in,
                              void* d_out, int out_size) {
    int ei_pos = -1;
    for (int i = 0; i < n_in; i++) if (in_sizes[i] == 2*EE) { ei_pos = i; break; }
    const float* p[25]; int j = 0;
    for (int i = 0; i < n_in; i++) { if (i == ei_pos) continue; p[j++] = (const float*)d_in[i]; }
    const float *node = p[0], *rbf = p[1], *rsh = p[2], *gs = p[3], *bs = p[4], *gv = p[5],
                *WsS = p[6], *WvS = p[7], *WsD = p[8], *WvD = p[9], *Wr = p[10],
                *Wa = p[11], *ad = p[12], *Wval = p[13], *Wvv = p[14], *Wg = p[15],
                *w2ss = p[16], *w2sv = p[17], *w2vs = p[18], *w2v0 = p[19], *w2v1 = p[20],
                *Wvl = p[21], *Wvv2 = p[22], *Wps = p[23], *Wpv = p[24];
    const int* ei = (const int*)d_in[ei_pos];
    float* out = (float*)d_out;

    cudaFuncSetAttribute(k_edge1, cudaFuncAttributeMaxDynamicSharedMemorySize, 23104*4);
    cudaFuncSetAttribute(k_edge2, cudaFuncAttributeMaxDynamicSharedMemorySize, 55008*4);

    k_init<<<256, 256>>>();
    k_node<<<(NN*32 + 255)/256, 256>>>(node, gs, bs, gv, WsS, WvS, WsD, WvD);
    k_edge1<<<148, 512, 23104*4>>>(ei, rbf, rsh, Wr, Wa, ad);
    k_soft<<<(EE*4 + 255)/256, 256>>>(ei);
    k_edge2<<<148, 448, 55008*4>>>(ei, rbf, rsh, Wr, Wval, Wvv, Wg,
                                   w2ss, w2sv, w2vs, w2v0, w2v1, Wvl, Wvv2);
    k_out<<<(NN*32 + 255)/256, 256>>>(node, Wps, Wpv, out);
}